// round 2
// baseline (speedup 1.0000x reference)
#include <cuda_runtime.h>
#include <cuda_bf16.h>

#define Bb 4
#define Nn 4096
#define Dd 1024
#define Hh 16
#define DKk 64
#define Mm 256
#define TD 3072           // 3*D
#define Rr (Bb*Nn)        // 16384
#define BH (Bb*Hh)        // 64
#define SPLITS 8
#define EPSc 1e-6f

// ---------------- scratch (device globals; no cudaMalloc allowed) -----------
__device__ float g_qkv[(size_t)Rr*TD];            // 192 MB
__device__ float g_Qp[(size_t)BH*Nn*Mm];          // 64 MB
__device__ float g_Kp[(size_t)BH*Nn*Mm];          // 64 MB
__device__ float g_KVp[(size_t)BH*SPLITS*Mm*65];  // 34 MB
__device__ float g_KV[(size_t)BH*Mm*65];          // 4 MB
__device__ float g_ctx[(size_t)Rr*Dd];            // 64 MB
__device__ unsigned char g_mask[Rr];              // normalized pad mask (1 = PAD)

// ---------------- mask dtype sniffing + normalization -----------------------
// If the mask arrives as int32 {0,1}, every 4-byte word is <= 1. If it arrives
// as 1-byte bools, words of 4 packed random bools exceed 1 almost surely.
__global__ __launch_bounds__(1024) void normalize_mask_kernel(const unsigned char* raw)
{
    __shared__ int wide_bytes;
    const unsigned int* w = (const unsigned int*)raw;
    int t = threadIdx.x;
    if (t == 0) wide_bytes = 0;
    __syncthreads();
    int bad = 0;
    for (int i = t; i < Rr/4; i += 1024)
        if (w[i] > 1u) bad = 1;
    if (bad) atomicOr(&wide_bytes, 1);
    __syncthreads();
    if (wide_bytes) {           // byte-bool layout
        for (int i = t; i < Rr; i += 1024) g_mask[i] = raw[i] ? 1 : 0;
    } else {                    // int32 layout
        for (int i = t; i < Rr; i += 1024) g_mask[i] = w[i] ? 1 : 0;
    }
}

// ---------------- fast exp (FMA-pipe, avoids MUFU bottleneck) ---------------
__device__ __forceinline__ float fast_exp_neg(float z) {
    // z <= 0 (post max-subtraction). exp(z) = 2^(z*log2e)
    float y = z * 1.4426950408889634f;
    y = fmaxf(y, -125.0f);
    float t = y + 12582912.0f;                       // round-to-nearest-int trick
    int   i = __float_as_int(t) - 0x4B400000;
    float f = y - (t - 12582912.0f);                 // f in [-0.5, 0.5]
    float p = 1.5403530393381609e-4f;
    p = fmaf(p, f, 1.3333558146428443e-3f);
    p = fmaf(p, f, 9.618129107628477e-3f);
    p = fmaf(p, f, 5.550410866482158e-2f);
    p = fmaf(p, f, 2.402265069591007e-1f);
    p = fmaf(p, f, 6.931471805599453e-1f);
    p = fmaf(p, f, 1.0f);
    return __int_as_float(__float_as_int(p) + (i << 23));
}

// ---------------- generic NT SGEMM: C[r][c] = sum_k A[r][k]*W[c][k] + b[c] --
// 64x64 tile, BK=16, 256 threads, 4x4 frags. Optional pad mask on rows.
__global__ __launch_bounds__(256) void gemm_nt_kernel(
    const float* __restrict__ A, const float* __restrict__ W,
    const float* __restrict__ bias, float* __restrict__ C,
    int K, int Ccols, const unsigned char* __restrict__ pad)
{
    __shared__ float As[16*68];
    __shared__ float Ws[16*68];
    int tid = threadIdx.x;
    int row0 = blockIdx.y * 64, col0 = blockIdx.x * 64;
    int lr = tid >> 2;
    int lk = (tid & 3) * 4;
    int ty = tid >> 4, tx = tid & 15;
    float acc[4][4] = {};
    for (int k0 = 0; k0 < K; k0 += 16) {
        float4 a4 = *(const float4*)&A[(size_t)(row0 + lr) * K + k0 + lk];
        float4 w4 = *(const float4*)&W[(size_t)(col0 + lr) * K + k0 + lk];
        __syncthreads();
        As[(lk+0)*68+lr] = a4.x; As[(lk+1)*68+lr] = a4.y;
        As[(lk+2)*68+lr] = a4.z; As[(lk+3)*68+lr] = a4.w;
        Ws[(lk+0)*68+lr] = w4.x; Ws[(lk+1)*68+lr] = w4.y;
        Ws[(lk+2)*68+lr] = w4.z; Ws[(lk+3)*68+lr] = w4.w;
        __syncthreads();
        #pragma unroll
        for (int k = 0; k < 16; k++) {
            float4 av = *(const float4*)&As[k*68 + ty*4];
            float4 wv = *(const float4*)&Ws[k*68 + tx*4];
            float a[4] = {av.x, av.y, av.z, av.w};
            float w[4] = {wv.x, wv.y, wv.z, wv.w};
            #pragma unroll
            for (int i = 0; i < 4; i++)
                #pragma unroll
                for (int j = 0; j < 4; j++)
                    acc[i][j] = fmaf(a[i], w[j], acc[i][j]);
        }
    }
    #pragma unroll
    for (int i = 0; i < 4; i++) {
        int r = row0 + ty*4 + i;
        float vm = 1.0f;
        if (pad) vm = pad[r] ? 0.0f : 1.0f;
        #pragma unroll
        for (int j = 0; j < 4; j++) {
            int c = col0 + tx*4 + j;
            C[(size_t)r * Ccols + c] = (acc[i][j] + bias[c]) * vm;
        }
    }
}

// ---------------- phi: proj = t @ omega[h]^T; exp(proj - rowmax)/sqrt(M) ----
// block: 32 n-rows x all 256 features for one (b,h,q-or-k). omega tile in smem.
#define PHI_SMEM ((64*256 + 32*68 + 32*260) * 4)
__global__ __launch_bounds__(256) void phi_kernel(
    const float* __restrict__ qkv, const float* __restrict__ omega,
    const unsigned char* __restrict__ pad,
    float* __restrict__ Qp, float* __restrict__ Kp)
{
    extern __shared__ float sm[];
    float* w_s = sm;                 // [64][256]
    float* a_s = sm + 64*256;        // [32][68]
    float* p_s = a_s + 32*68;        // [32][260]
    int tid = threadIdx.x;
    int bh = blockIdx.y; int b = bh >> 4, h = bh & 15;
    int qk = blockIdx.z;
    int n0 = blockIdx.x * 32;

    // omega[h] -> w_s[k][m] (transposed)
    {
        const float* op = omega + ((size_t)h * Mm + tid) * DKk;
        #pragma unroll
        for (int k0 = 0; k0 < 64; k0 += 4) {
            float4 v = *(const float4*)(op + k0);
            w_s[(k0+0)*256+tid] = v.x; w_s[(k0+1)*256+tid] = v.y;
            w_s[(k0+2)*256+tid] = v.z; w_s[(k0+3)*256+tid] = v.w;
        }
    }
    // t rows -> a_s
    {
        int r = tid >> 3; int k0 = (tid & 7) * 8;
        const float* tp = qkv + (size_t)(b*Nn + n0 + r) * TD + qk * Dd + h * DKk;
        float4 v0 = *(const float4*)(tp + k0);
        float4 v1 = *(const float4*)(tp + k0 + 4);
        *(float4*)&a_s[r*68 + k0]     = v0;
        *(float4*)&a_s[r*68 + k0 + 4] = v1;
    }
    __syncthreads();

    int tcol = tid & 63, trow = tid >> 6;        // 64 col-groups x 4 row-groups
    float acc[8][4] = {};
    #pragma unroll 8
    for (int k = 0; k < 64; k++) {
        float4 w4 = *(const float4*)&w_s[k*256 + tcol*4];
        #pragma unroll
        for (int r = 0; r < 8; r++) {
            float a = a_s[(trow*8 + r)*68 + k];
            acc[r][0] = fmaf(a, w4.x, acc[r][0]);
            acc[r][1] = fmaf(a, w4.y, acc[r][1]);
            acc[r][2] = fmaf(a, w4.z, acc[r][2]);
            acc[r][3] = fmaf(a, w4.w, acc[r][3]);
        }
    }
    #pragma unroll
    for (int r = 0; r < 8; r++)
        *(float4*)&p_s[(trow*8 + r)*260 + tcol*4] =
            make_float4(acc[r][0], acc[r][1], acc[r][2], acc[r][3]);
    __syncthreads();

    // phase 2: per-row max, exp, scale, (mask for K), store
    int wid = tid >> 5, lane = tid & 31;
    float* outp = qk ? Kp : Qp;
    #pragma unroll
    for (int rr = 0; rr < 4; rr++) {
        int row = wid * 4 + rr;
        int n = n0 + row;
        float v[8]; float mx = -1e30f;
        #pragma unroll
        for (int i = 0; i < 8; i++) {
            v[i] = p_s[row*260 + i*32 + lane];
            mx = fmaxf(mx, v[i]);
        }
        #pragma unroll
        for (int o = 16; o; o >>= 1) mx = fmaxf(mx, __shfl_xor_sync(0xffffffffu, mx, o));
        float scale = 0.0625f;  // 1/sqrt(256+1e-6)
        if (qk && pad[b*Nn + n]) scale = 0.0f;
        float* dst = outp + ((size_t)bh * Nn + n) * Mm;
        #pragma unroll
        for (int i = 0; i < 8; i++)
            dst[i*32 + lane] = fast_exp_neg(v[i] - mx) * scale;
    }
}

// ---------------- KV partial: KVp[bh][s][m][d<64]=sum Kp*V ; col64 = ksum ---
__global__ __launch_bounds__(256) void kv_kernel(
    const float* __restrict__ Kp, const float* __restrict__ qkv,
    float* __restrict__ KVp)
{
    __shared__ float kps[32*260];
    __shared__ float vs[32*68];
    int tid = threadIdx.x;
    int s = blockIdx.x, bh = blockIdx.y;
    int b = bh >> 4, h = bh & 15;
    int tm = tid & 63, td = tid >> 6;    // 64 m-groups(4) x 4 d-groups(16)
    float acc[4][16] = {};
    float ks[4] = {0.f, 0.f, 0.f, 0.f};

    for (int n0 = s * (Nn/SPLITS); n0 < (s+1) * (Nn/SPLITS); n0 += 32) {
        __syncthreads();
        {   // Kp tile 32x256
            int r = tid >> 3; int f = tid & 7;
            const float* src = Kp + ((size_t)bh * Nn + n0 + r) * Mm;
            #pragma unroll
            for (int j = 0; j < 8; j++) {
                float4 v = *(const float4*)(src + (f + j*8) * 4);
                *(float4*)&kps[r*260 + (f + j*8)*4] = v;
            }
        }
        {   // V tile 32x64
            int r = tid >> 3; int d0 = (tid & 7) * 8;
            const float* src = qkv + (size_t)(b*Nn + n0 + r) * TD + 2*Dd + h*DKk;
            *(float4*)&vs[r*68 + d0]     = *(const float4*)(src + d0);
            *(float4*)&vs[r*68 + d0 + 4] = *(const float4*)(src + d0 + 4);
        }
        __syncthreads();
        #pragma unroll 2
        for (int nn = 0; nn < 32; nn++) {
            float4 k4 = *(const float4*)&kps[nn*260 + tm*4];
            float kk[4] = {k4.x, k4.y, k4.z, k4.w};
            if (td == 0) {   // uniform per warp
                ks[0] += kk[0]; ks[1] += kk[1]; ks[2] += kk[2]; ks[3] += kk[3];
            }
            float4 v0 = *(const float4*)&vs[nn*68 + td*16];
            float4 v1 = *(const float4*)&vs[nn*68 + td*16 + 4];
            float4 v2 = *(const float4*)&vs[nn*68 + td*16 + 8];
            float4 v3 = *(const float4*)&vs[nn*68 + td*16 + 12];
            float vv[16] = {v0.x,v0.y,v0.z,v0.w, v1.x,v1.y,v1.z,v1.w,
                            v2.x,v2.y,v2.z,v2.w, v3.x,v3.y,v3.z,v3.w};
            #pragma unroll
            for (int j = 0; j < 4; j++)
                #pragma unroll
                for (int dd = 0; dd < 16; dd++)
                    acc[j][dd] = fmaf(kk[j], vv[dd], acc[j][dd]);
        }
    }
    size_t base = ((size_t)(bh * SPLITS + s)) * Mm * 65;
    #pragma unroll
    for (int j = 0; j < 4; j++) {
        int m = tm*4 + j;
        #pragma unroll
        for (int dd = 0; dd < 16; dd++)
            KVp[base + (size_t)m*65 + td*16 + dd] = acc[j][dd];
        if (td == 0) KVp[base + (size_t)m*65 + 64] = ks[j];
    }
}

__global__ void kv_reduce_kernel(const float* __restrict__ KVp, float* __restrict__ KV)
{
    int e = blockIdx.x * blockDim.x + threadIdx.x;
    const int per = Mm * 65;
    if (e >= BH * per) return;
    int bh = e / per; int r = e - bh * per;
    float sum = 0.f;
    #pragma unroll
    for (int sp = 0; sp < SPLITS; sp++)
        sum += KVp[((size_t)(bh * SPLITS + sp)) * per + r];
    KV[e] = sum;
}

// ---------------- ctx = (Qp@KV) / (Qp@ksum + eps) ---------------------------
#define CTX_SMEM ((256*68 + 32*68 + 64) * 4)
__global__ __launch_bounds__(256) void ctx_kernel(
    const float* __restrict__ Qp, const float* __restrict__ KV,
    float* __restrict__ ctx)
{
    extern __shared__ float sm[];
    float* kvs   = sm;               // [256][68] (65 used)
    float* qs    = sm + 256*68;      // [32][68]
    float* den_s = qs + 32*68;       // [64]
    int tid = threadIdx.x;
    int bh = blockIdx.y; int b = bh >> 4, h = bh & 15;
    int n0 = blockIdx.x * 64;

    for (int e = tid; e < Mm*65; e += 256) {
        int m = e / 65, d = e - m*65;
        kvs[m*68 + d] = KV[(size_t)bh * Mm * 65 + e];
    }
    int ty = tid >> 4, tx = tid & 15;
    float acc[4][4] = {};
    float den = 0.f;
    for (int k0 = 0; k0 < Mm; k0 += 32) {
        int lr = tid >> 2; int lk = (tid & 3) * 8;
        const float* src = Qp + ((size_t)bh * Nn + n0 + lr) * Mm + k0 + lk;
        float4 v0 = *(const float4*)src;
        float4 v1 = *(const float4*)(src + 4);
        __syncthreads();
        qs[(lk+0)*68+lr] = v0.x; qs[(lk+1)*68+lr] = v0.y;
        qs[(lk+2)*68+lr] = v0.z; qs[(lk+3)*68+lr] = v0.w;
        qs[(lk+4)*68+lr] = v1.x; qs[(lk+5)*68+lr] = v1.y;
        qs[(lk+6)*68+lr] = v1.z; qs[(lk+7)*68+lr] = v1.w;
        __syncthreads();
        #pragma unroll 8
        for (int k = 0; k < 32; k++) {
            float4 qv = *(const float4*)&qs[k*68 + ty*4];
            float4 wv = *(const float4*)&kvs[(k0+k)*68 + tx*4];
            float q[4] = {qv.x, qv.y, qv.z, qv.w};
            float w[4] = {wv.x, wv.y, wv.z, wv.w};
            #pragma unroll
            for (int i = 0; i < 4; i++)
                #pragma unroll
                for (int j = 0; j < 4; j++)
                    acc[i][j] = fmaf(q[i], w[j], acc[i][j]);
        }
        if (tid < 64) {
            #pragma unroll 8
            for (int k = 0; k < 32; k++)
                den = fmaf(qs[k*68 + tid], kvs[(k0+k)*68 + 64], den);
        }
    }
    if (tid < 64) den_s[tid] = den;
    __syncthreads();
    #pragma unroll
    for (int i = 0; i < 4; i++) {
        int n = n0 + ty*4 + i;
        float dv = den_s[ty*4 + i] + EPSc;
        float inv = 1.0f / dv;
        #pragma unroll
        for (int j = 0; j < 4; j++)
            ctx[(size_t)(b*Nn + n) * Dd + h*DKk + tx*4 + j] = acc[i][j] * inv;
    }
}

// ---------------- launch ----------------------------------------------------
extern "C" void kernel_launch(void* const* d_in, const int* in_sizes, int n_in,
                              void* d_out, int out_size)
{
    // Select inputs by element count (order-proof). All sizes are distinct:
    // x=16777216, mask=16384, Wqkv=3145728, bqkv=3072, Wout=1048576,
    // bout=1024, omega=262144.
    const float *x = 0, *Wqkv = 0, *bqkv = 0, *Wout = 0, *bout = 0, *omega = 0;
    const unsigned char* mraw = 0;
    for (int i = 0; i < n_in; i++) {
        switch (in_sizes[i]) {
            case 16777216: x     = (const float*)d_in[i]; break;
            case 16384:    mraw  = (const unsigned char*)d_in[i]; break;
            case 3145728:  Wqkv  = (const float*)d_in[i]; break;
            case 3072:     bqkv  = (const float*)d_in[i]; break;
            case 1048576:  Wout  = (const float*)d_in[i]; break;
            case 1024:     bout  = (const float*)d_in[i]; break;
            case 262144:   omega = (const float*)d_in[i]; break;
            default: break;
        }
    }
    float* out = (float*)d_out;

    float *qkv, *Qp, *Kp, *KVp, *KV, *ctx;
    unsigned char* mask;
    cudaGetSymbolAddress((void**)&qkv,  g_qkv);
    cudaGetSymbolAddress((void**)&Qp,   g_Qp);
    cudaGetSymbolAddress((void**)&Kp,   g_Kp);
    cudaGetSymbolAddress((void**)&KVp,  g_KVp);
    cudaGetSymbolAddress((void**)&KV,   g_KV);
    cudaGetSymbolAddress((void**)&ctx,  g_ctx);
    cudaGetSymbolAddress((void**)&mask, g_mask);

    cudaFuncSetAttribute(phi_kernel, cudaFuncAttributeMaxDynamicSharedMemorySize, PHI_SMEM);
    cudaFuncSetAttribute(ctx_kernel, cudaFuncAttributeMaxDynamicSharedMemorySize, CTX_SMEM);

    // 0) sniff mask dtype (int32 vs byte-bool) and normalize to uint8
    normalize_mask_kernel<<<1, 1024>>>(mraw);
    // 1) qkv = x @ Wqkv^T + bqkv
    gemm_nt_kernel<<<dim3(TD/64, Rr/64), 256>>>(x, Wqkv, bqkv, qkv, Dd, TD, nullptr);
    // 2) Qp / Kp features
    phi_kernel<<<dim3(Nn/32, BH, 2), 256, PHI_SMEM>>>(qkv, omega, mask, Qp, Kp);
    // 3) KV + ksum (split-K, deterministic two-stage)
    kv_kernel<<<dim3(SPLITS, BH), 256>>>(Kp, qkv, KVp);
    kv_reduce_kernel<<<(BH*Mm*65 + 255)/256, 256>>>(KVp, KV);
    // 4) ctx
    ctx_kernel<<<dim3(Nn/64, BH), 256, CTX_SMEM>>>(Qp, KV, ctx);
    // 5) out = (ctx @ Wout^T + bout) * valid
    gemm_nt_kernel<<<dim3(Dd/64, Rr/64), 256>>>(ctx, Wout, bout, out, Dd, Dd, mask);
}

// round 4
// speedup vs baseline: 1.4544x; 1.4544x over previous
#include <cuda_runtime.h>
#include <cuda_bf16.h>
#include <cstdint>

#define Bb 4
#define Nn 4096
#define Dd 1024
#define Hh 16
#define DKk 64
#define Mm 256
#define TD 3072           // 3*D
#define Rr (Bb*Nn)        // 16384
#define BH (Bb*Hh)        // 64
#define SPLITS 8
#define EPSc 1e-6f

// ---------------- scratch (device globals; no cudaMalloc allowed) -----------
__device__ float g_qkv[(size_t)Rr*TD];            // 192 MB
__device__ float g_Qp[(size_t)BH*Nn*Mm];          // 64 MB
__device__ float g_Kp[(size_t)BH*Nn*Mm];          // 64 MB
__device__ float g_KVp[(size_t)BH*SPLITS*Mm*65];  // 34 MB
__device__ float g_KV[(size_t)BH*Mm*65];          // 4 MB
__device__ float g_ctx[(size_t)Rr*Dd];            // 64 MB
__device__ unsigned char g_mask[Rr];              // normalized pad mask (1 = PAD)

// ---------------- 3xTF32 helpers --------------------------------------------
__device__ __forceinline__ float to_tf32(float x) {
    float r; asm("cvt.rna.tf32.f32 %0, %1;" : "=f"(r) : "f"(x)); return r;
}
__device__ __forceinline__ void mma_tf32(float* c, uint32_t a0, uint32_t a1,
                                         uint32_t a2, uint32_t a3,
                                         uint32_t b0, uint32_t b1) {
    asm volatile(
        "mma.sync.aligned.m16n8k8.row.col.f32.tf32.tf32.f32 "
        "{%0,%1,%2,%3}, {%4,%5,%6,%7}, {%8,%9}, {%0,%1,%2,%3};"
        : "+f"(c[0]), "+f"(c[1]), "+f"(c[2]), "+f"(c[3])
        : "r"(a0), "r"(a1), "r"(a2), "r"(a3), "r"(b0), "r"(b1));
}

// ================= mma.sync NT GEMM (3xTF32, fp32-accurate) =================
// C[R x Ccols] = A[R x K] @ W[Ccols x K]^T + bias, optional row mask.
// Block 128x128, BK=32, 256 threads = 8 warps (2m x 4n), warp tile 64x32.
#define MBM 128
#define MBN 128
#define MBK 32
#define PADF 36                       // row stride in floats; (t/4)*36+(t%4) -> bank = t
#define MG_AH 0
#define MG_AL (128*PADF)
#define MG_BH (2*128*PADF)
#define MG_BL (3*128*PADF)
#define MG_SMEM (4*128*PADF*4)        // 73728 bytes

__global__ __launch_bounds__(256) void mma_gemm_kernel(
    const float* __restrict__ A, const float* __restrict__ W,
    const float* __restrict__ bias, float* __restrict__ C,
    int K, int Ccols, const unsigned char* __restrict__ pad)
{
    extern __shared__ float sm[];
    int tid = threadIdx.x, wid = tid >> 5, tl = tid & 31;
    int wm = wid & 1, wn = wid >> 1;          // warp grid 2(m) x 4(n)
    int row0 = blockIdx.y * MBM, col0 = blockIdx.x * MBN;
    const float* Abase = A + (size_t)row0 * K;
    const float* Wbase = W + (size_t)col0 * K;

    int ar = tl >> 2, ac = tl & 3;            // frag lane decomposition

    float acc[4][4][4];
    #pragma unroll
    for (int i = 0; i < 4; i++)
        #pragma unroll
        for (int j = 0; j < 4; j++)
            #pragma unroll
            for (int e = 0; e < 4; e++) acc[i][j][e] = 0.f;

    float4 a4[4], b4[4];
    {   // prefetch k-chunk 0
        #pragma unroll
        for (int j = 0; j < 4; j++) {
            int idx = j*256 + tid;
            a4[j] = *(const float4*)(Abase + (size_t)(idx>>3) * K + (idx&7)*4);
            b4[j] = *(const float4*)(Wbase + (size_t)(idx>>3) * K + (idx&7)*4);
        }
    }

    const int NK = K / MBK;
    for (int i = 0; i < NK; i++) {
        // split + store to smem
        #pragma unroll
        for (int j = 0; j < 4; j++) {
            int idx = j*256 + tid;
            int off = (idx>>3)*PADF + (idx&7)*4;
            float4 v = a4[j];
            float4 h = make_float4(to_tf32(v.x), to_tf32(v.y), to_tf32(v.z), to_tf32(v.w));
            float4 l = make_float4(to_tf32(v.x-h.x), to_tf32(v.y-h.y),
                                   to_tf32(v.z-h.z), to_tf32(v.w-h.w));
            *(float4*)&sm[MG_AH + off] = h;
            *(float4*)&sm[MG_AL + off] = l;
            v = b4[j];
            h = make_float4(to_tf32(v.x), to_tf32(v.y), to_tf32(v.z), to_tf32(v.w));
            l = make_float4(to_tf32(v.x-h.x), to_tf32(v.y-h.y),
                            to_tf32(v.z-h.z), to_tf32(v.w-h.w));
            *(float4*)&sm[MG_BH + off] = h;
            *(float4*)&sm[MG_BL + off] = l;
        }
        if (i + 1 < NK) {   // prefetch next chunk
            int k0 = (i + 1) * MBK;
            #pragma unroll
            for (int j = 0; j < 4; j++) {
                int idx = j*256 + tid;
                a4[j] = *(const float4*)(Abase + (size_t)(idx>>3) * K + k0 + (idx&7)*4);
                b4[j] = *(const float4*)(Wbase + (size_t)(idx>>3) * K + k0 + (idx&7)*4);
            }
        }
        __syncthreads();

        #pragma unroll
        for (int ks = 0; ks < 4; ks++) {
            int kb = ks * 8;
            uint32_t bh[4][2], bl[4][2];
            #pragma unroll
            for (int ni = 0; ni < 4; ni++) {
                int n = wn*32 + ni*8 + ar;
                bh[ni][0] = __float_as_uint(sm[MG_BH + n*PADF + kb + ac]);
                bh[ni][1] = __float_as_uint(sm[MG_BH + n*PADF + kb + 4 + ac]);
                bl[ni][0] = __float_as_uint(sm[MG_BL + n*PADF + kb + ac]);
                bl[ni][1] = __float_as_uint(sm[MG_BL + n*PADF + kb + 4 + ac]);
            }
            #pragma unroll
            for (int mi = 0; mi < 4; mi++) {
                int m = wm*64 + mi*16 + ar;
                uint32_t ah0 = __float_as_uint(sm[MG_AH + m*PADF + kb + ac]);
                uint32_t ah1 = __float_as_uint(sm[MG_AH + (m+8)*PADF + kb + ac]);
                uint32_t ah2 = __float_as_uint(sm[MG_AH + m*PADF + kb + 4 + ac]);
                uint32_t ah3 = __float_as_uint(sm[MG_AH + (m+8)*PADF + kb + 4 + ac]);
                uint32_t al0 = __float_as_uint(sm[MG_AL + m*PADF + kb + ac]);
                uint32_t al1 = __float_as_uint(sm[MG_AL + (m+8)*PADF + kb + ac]);
                uint32_t al2 = __float_as_uint(sm[MG_AL + m*PADF + kb + 4 + ac]);
                uint32_t al3 = __float_as_uint(sm[MG_AL + (m+8)*PADF + kb + 4 + ac]);
                #pragma unroll
                for (int ni = 0; ni < 4; ni++) {
                    mma_tf32(acc[mi][ni], ah0, ah1, ah2, ah3, bh[ni][0], bh[ni][1]);
                    mma_tf32(acc[mi][ni], ah0, ah1, ah2, ah3, bl[ni][0], bl[ni][1]);
                    mma_tf32(acc[mi][ni], al0, al1, al2, al3, bh[ni][0], bh[ni][1]);
                }
            }
        }
        __syncthreads();
    }

    // epilogue: c0,c1 -> (row, col..col+1); c2,c3 -> (row+8, ..)
    #pragma unroll
    for (int mi = 0; mi < 4; mi++) {
        int r0 = row0 + wm*64 + mi*16 + ar;
        float vm0 = 1.0f, vm1 = 1.0f;
        if (pad) { vm0 = pad[r0] ? 0.0f : 1.0f; vm1 = pad[r0+8] ? 0.0f : 1.0f; }
        #pragma unroll
        for (int ni = 0; ni < 4; ni++) {
            int c = col0 + wn*32 + ni*8 + ac*2;
            float b0 = bias[c], b1 = bias[c+1];
            *(float2*)&C[(size_t)r0 * Ccols + c] =
                make_float2((acc[mi][ni][0] + b0) * vm0, (acc[mi][ni][1] + b1) * vm0);
            *(float2*)&C[(size_t)(r0+8) * Ccols + c] =
                make_float2((acc[mi][ni][2] + b0) * vm1, (acc[mi][ni][3] + b1) * vm1);
        }
    }
}

// ---------------- mask dtype sniffing + normalization -----------------------
__global__ __launch_bounds__(1024) void normalize_mask_kernel(const unsigned char* raw)
{
    __shared__ int wide_bytes;
    const unsigned int* w = (const unsigned int*)raw;
    int t = threadIdx.x;
    if (t == 0) wide_bytes = 0;
    __syncthreads();
    int bad = 0;
    for (int i = t; i < Rr/4; i += 1024)
        if (w[i] > 1u) bad = 1;
    if (bad) atomicOr(&wide_bytes, 1);
    __syncthreads();
    if (wide_bytes) {
        for (int i = t; i < Rr; i += 1024) g_mask[i] = raw[i] ? 1 : 0;
    } else {
        for (int i = t; i < Rr; i += 1024) g_mask[i] = w[i] ? 1 : 0;
    }
}

// ---------------- fast exp (FMA-pipe, avoids MUFU bottleneck) ---------------
__device__ __forceinline__ float fast_exp_neg(float z) {
    float y = z * 1.4426950408889634f;
    y = fmaxf(y, -125.0f);
    float t = y + 12582912.0f;
    int   i = __float_as_int(t) - 0x4B400000;
    float f = y - (t - 12582912.0f);
    float p = 1.5403530393381609e-4f;
    p = fmaf(p, f, 1.3333558146428443e-3f);
    p = fmaf(p, f, 9.618129107628477e-3f);
    p = fmaf(p, f, 5.550410866482158e-2f);
    p = fmaf(p, f, 2.402265069591007e-1f);
    p = fmaf(p, f, 6.931471805599453e-1f);
    p = fmaf(p, f, 1.0f);
    return __int_as_float(__float_as_int(p) + (i << 23));
}

// ---------------- phi: proj = t @ omega[h]^T; exp(proj - rowmax)/sqrt(M) ----
#define PHI_SMEM ((64*256 + 32*68 + 32*260) * 4)
__global__ __launch_bounds__(256) void phi_kernel(
    const float* __restrict__ qkv, const float* __restrict__ omega,
    const unsigned char* __restrict__ pad,
    float* __restrict__ Qp, float* __restrict__ Kp)
{
    extern __shared__ float smf[];
    float* w_s = smf;                 // [64][256]
    float* a_s = smf + 64*256;        // [32][68]
    float* p_s = a_s + 32*68;         // [32][260]
    int tid = threadIdx.x;
    int bh = blockIdx.y; int b = bh >> 4, h = bh & 15;
    int qk = blockIdx.z;
    int n0 = blockIdx.x * 32;

    {
        const float* op = omega + ((size_t)h * Mm + tid) * DKk;
        #pragma unroll
        for (int k0 = 0; k0 < 64; k0 += 4) {
            float4 v = *(const float4*)(op + k0);
            w_s[(k0+0)*256+tid] = v.x; w_s[(k0+1)*256+tid] = v.y;
            w_s[(k0+2)*256+tid] = v.z; w_s[(k0+3)*256+tid] = v.w;
        }
    }
    {
        int r = tid >> 3; int k0 = (tid & 7) * 8;
        const float* tp = qkv + (size_t)(b*Nn + n0 + r) * TD + qk * Dd + h * DKk;
        float4 v0 = *(const float4*)(tp + k0);
        float4 v1 = *(const float4*)(tp + k0 + 4);
        *(float4*)&a_s[r*68 + k0]     = v0;
        *(float4*)&a_s[r*68 + k0 + 4] = v1;
    }
    __syncthreads();

    int tcol = tid & 63, trow = tid >> 6;
    float acc[8][4] = {};
    #pragma unroll 8
    for (int k = 0; k < 64; k++) {
        float4 w4 = *(const float4*)&w_s[k*256 + tcol*4];
        #pragma unroll
        for (int r = 0; r < 8; r++) {
            float a = a_s[(trow*8 + r)*68 + k];
            acc[r][0] = fmaf(a, w4.x, acc[r][0]);
            acc[r][1] = fmaf(a, w4.y, acc[r][1]);
            acc[r][2] = fmaf(a, w4.z, acc[r][2]);
            acc[r][3] = fmaf(a, w4.w, acc[r][3]);
        }
    }
    #pragma unroll
    for (int r = 0; r < 8; r++)
        *(float4*)&p_s[(trow*8 + r)*260 + tcol*4] =
            make_float4(acc[r][0], acc[r][1], acc[r][2], acc[r][3]);
    __syncthreads();

    int wid = tid >> 5, lane = tid & 31;
    float* outp = qk ? Kp : Qp;
    #pragma unroll
    for (int rr = 0; rr < 4; rr++) {
        int row = wid * 4 + rr;
        int n = n0 + row;
        float v[8]; float mx = -1e30f;
        #pragma unroll
        for (int i = 0; i < 8; i++) {
            v[i] = p_s[row*260 + i*32 + lane];
            mx = fmaxf(mx, v[i]);
        }
        #pragma unroll
        for (int o = 16; o; o >>= 1) mx = fmaxf(mx, __shfl_xor_sync(0xffffffffu, mx, o));
        float scale = 0.0625f;
        if (qk && pad[b*Nn + n]) scale = 0.0f;
        float* dst = outp + ((size_t)bh * Nn + n) * Mm;
        #pragma unroll
        for (int i = 0; i < 8; i++)
            dst[i*32 + lane] = fast_exp_neg(v[i] - mx) * scale;
    }
}

// ---------------- KV partial: KVp[bh][s][m][d<64]=sum Kp*V ; col64 = ksum ---
__global__ __launch_bounds__(256) void kv_kernel(
    const float* __restrict__ Kp, const float* __restrict__ qkv,
    float* __restrict__ KVp)
{
    __shared__ float kps[32*260];
    __shared__ float vs[32*68];
    int tid = threadIdx.x;
    int s = blockIdx.x, bh = blockIdx.y;
    int b = bh >> 4, h = bh & 15;
    int tm = tid & 63, td = tid >> 6;
    float acc[4][16] = {};
    float ks[4] = {0.f, 0.f, 0.f, 0.f};

    for (int n0 = s * (Nn/SPLITS); n0 < (s+1) * (Nn/SPLITS); n0 += 32) {
        __syncthreads();
        {
            int r = tid >> 3; int f = tid & 7;
            const float* src = Kp + ((size_t)bh * Nn + n0 + r) * Mm;
            #pragma unroll
            for (int j = 0; j < 8; j++) {
                float4 v = *(const float4*)(src + (f + j*8) * 4);
                *(float4*)&kps[r*260 + (f + j*8)*4] = v;
            }
        }
        {
            int r = tid >> 3; int d0 = (tid & 7) * 8;
            const float* src = qkv + (size_t)(b*Nn + n0 + r) * TD + 2*Dd + h*DKk;
            *(float4*)&vs[r*68 + d0]     = *(const float4*)(src + d0);
            *(float4*)&vs[r*68 + d0 + 4] = *(const float4*)(src + d0 + 4);
        }
        __syncthreads();
        #pragma unroll 2
        for (int nn = 0; nn < 32; nn++) {
            float4 k4 = *(const float4*)&kps[nn*260 + tm*4];
            float kk[4] = {k4.x, k4.y, k4.z, k4.w};
            if (td == 0) {
                ks[0] += kk[0]; ks[1] += kk[1]; ks[2] += kk[2]; ks[3] += kk[3];
            }
            float4 v0 = *(const float4*)&vs[nn*68 + td*16];
            float4 v1 = *(const float4*)&vs[nn*68 + td*16 + 4];
            float4 v2 = *(const float4*)&vs[nn*68 + td*16 + 8];
            float4 v3 = *(const float4*)&vs[nn*68 + td*16 + 12];
            float vv[16] = {v0.x,v0.y,v0.z,v0.w, v1.x,v1.y,v1.z,v1.w,
                            v2.x,v2.y,v2.z,v2.w, v3.x,v3.y,v3.z,v3.w};
            #pragma unroll
            for (int j = 0; j < 4; j++)
                #pragma unroll
                for (int dd = 0; dd < 16; dd++)
                    acc[j][dd] = fmaf(kk[j], vv[dd], acc[j][dd]);
        }
    }
    size_t base = ((size_t)(bh * SPLITS + s)) * Mm * 65;
    #pragma unroll
    for (int j = 0; j < 4; j++) {
        int m = tm*4 + j;
        #pragma unroll
        for (int dd = 0; dd < 16; dd++)
            KVp[base + (size_t)m*65 + td*16 + dd] = acc[j][dd];
        if (td == 0) KVp[base + (size_t)m*65 + 64] = ks[j];
    }
}

__global__ void kv_reduce_kernel(const float* __restrict__ KVp, float* __restrict__ KV)
{
    int e = blockIdx.x * blockDim.x + threadIdx.x;
    const int per = Mm * 65;
    if (e >= BH * per) return;
    int bh = e / per; int r = e - bh * per;
    float sum = 0.f;
    #pragma unroll
    for (int sp = 0; sp < SPLITS; sp++)
        sum += KVp[((size_t)(bh * SPLITS + sp)) * per + r];
    KV[e] = sum;
}

// ---------------- ctx = (Qp@KV) / (Qp@ksum + eps) ---------------------------
#define CTX_SMEM ((256*68 + 32*68 + 64) * 4)
__global__ __launch_bounds__(256) void ctx_kernel(
    const float* __restrict__ Qp, const float* __restrict__ KV,
    float* __restrict__ ctx)
{
    extern __shared__ float smf[];
    float* kvs   = smf;
    float* qs    = smf + 256*68;
    float* den_s = qs + 32*68;
    int tid = threadIdx.x;
    int bh = blockIdx.y; int b = bh >> 4, h = bh & 15;
    int n0 = blockIdx.x * 64;

    for (int e = tid; e < Mm*65; e += 256) {
        int m = e / 65, d = e - m*65;
        kvs[m*68 + d] = KV[(size_t)bh * Mm * 65 + e];
    }
    int ty = tid >> 4, tx = tid & 15;
    float acc[4][4] = {};
    float den = 0.f;
    for (int k0 = 0; k0 < Mm; k0 += 32) {
        int lr = tid >> 2; int lk = (tid & 3) * 8;
        const float* src = Qp + ((size_t)bh * Nn + n0 + lr) * Mm + k0 + lk;
        float4 v0 = *(const float4*)src;
        float4 v1 = *(const float4*)(src + 4);
        __syncthreads();
        qs[(lk+0)*68+lr] = v0.x; qs[(lk+1)*68+lr] = v0.y;
        qs[(lk+2)*68+lr] = v0.z; qs[(lk+3)*68+lr] = v0.w;
        qs[(lk+4)*68+lr] = v1.x; qs[(lk+5)*68+lr] = v1.y;
        qs[(lk+6)*68+lr] = v1.z; qs[(lk+7)*68+lr] = v1.w;
        __syncthreads();
        #pragma unroll 8
        for (int k = 0; k < 32; k++) {
            float4 qv = *(const float4*)&qs[k*68 + ty*4];
            float4 wv = *(const float4*)&kvs[(k0+k)*68 + tx*4];
            float q[4] = {qv.x, qv.y, qv.z, qv.w};
            float w[4] = {wv.x, wv.y, wv.z, wv.w};
            #pragma unroll
            for (int i = 0; i < 4; i++)
                #pragma unroll
                for (int j = 0; j < 4; j++)
                    acc[i][j] = fmaf(q[i], w[j], acc[i][j]);
        }
        if (tid < 64) {
            #pragma unroll 8
            for (int k = 0; k < 32; k++)
                den = fmaf(qs[k*68 + tid], kvs[(k0+k)*68 + 64], den);
        }
    }
    if (tid < 64) den_s[tid] = den;
    __syncthreads();
    #pragma unroll
    for (int i = 0; i < 4; i++) {
        int n = n0 + ty*4 + i;
        float dv = den_s[ty*4 + i] + EPSc;
        float inv = 1.0f / dv;
        #pragma unroll
        for (int j = 0; j < 4; j++)
            ctx[(size_t)(b*Nn + n) * Dd + h*DKk + tx*4 + j] = acc[i][j] * inv;
    }
}

// ---------------- launch ----------------------------------------------------
extern "C" void kernel_launch(void* const* d_in, const int* in_sizes, int n_in,
                              void* d_out, int out_size)
{
    const float *x = 0, *Wqkv = 0, *bqkv = 0, *Wout = 0, *bout = 0, *omega = 0;
    const unsigned char* mraw = 0;
    for (int i = 0; i < n_in; i++) {
        switch (in_sizes[i]) {
            case 16777216: x     = (const float*)d_in[i]; break;
            case 16384:    mraw  = (const unsigned char*)d_in[i]; break;
            case 3145728:  Wqkv  = (const float*)d_in[i]; break;
            case 3072:     bqkv  = (const float*)d_in[i]; break;
            case 1048576:  Wout  = (const float*)d_in[i]; break;
            case 1024:     bout  = (const float*)d_in[i]; break;
            case 262144:   omega = (const float*)d_in[i]; break;
            default: break;
        }
    }
    float* out = (float*)d_out;

    float *qkv, *Qp, *Kp, *KVp, *KV, *ctx;
    unsigned char* mask;
    cudaGetSymbolAddress((void**)&qkv,  g_qkv);
    cudaGetSymbolAddress((void**)&Qp,   g_Qp);
    cudaGetSymbolAddress((void**)&Kp,   g_Kp);
    cudaGetSymbolAddress((void**)&KVp,  g_KVp);
    cudaGetSymbolAddress((void**)&KV,   g_KV);
    cudaGetSymbolAddress((void**)&ctx,  g_ctx);
    cudaGetSymbolAddress((void**)&mask, g_mask);

    cudaFuncSetAttribute(phi_kernel, cudaFuncAttributeMaxDynamicSharedMemorySize, PHI_SMEM);
    cudaFuncSetAttribute(ctx_kernel, cudaFuncAttributeMaxDynamicSharedMemorySize, CTX_SMEM);
    cudaFuncSetAttribute(mma_gemm_kernel, cudaFuncAttributeMaxDynamicSharedMemorySize, MG_SMEM);

    // 0) sniff mask dtype and normalize to uint8
    normalize_mask_kernel<<<1, 1024>>>(mraw);
    // 1) qkv = x @ Wqkv^T + bqkv   (mma.sync 3xTF32)
    mma_gemm_kernel<<<dim3(TD/MBN, Rr/MBM), 256, MG_SMEM>>>(
        x, Wqkv, bqkv, qkv, Dd, TD, nullptr);
    // 2) Qp / Kp features
    phi_kernel<<<dim3(Nn/32, BH, 2), 256, PHI_SMEM>>>(qkv, omega, mask, Qp, Kp);
    // 3) KV + ksum (split-K, deterministic two-stage)
    kv_kernel<<<dim3(SPLITS, BH), 256>>>(Kp, qkv, KVp);
    kv_reduce_kernel<<<(BH*Mm*65 + 255)/256, 256>>>(KVp, KV);
    // 4) ctx
    ctx_kernel<<<dim3(Nn/64, BH), 256, CTX_SMEM>>>(Qp, KV, ctx);
    // 5) out = (ctx @ Wout^T + bout) * valid   (mma.sync 3xTF32)
    mma_gemm_kernel<<<dim3(Dd/MBN, Rr/MBM), 256, MG_SMEM>>>(
        ctx, Wout, bout, out, Dd, Dd, mask);
}

// round 5
// speedup vs baseline: 1.5904x; 1.0935x over previous
#include <cuda_runtime.h>
#include <cuda_bf16.h>
#include <cstdint>

#define Bb 4
#define Nn 4096
#define Dd 1024
#define Hh 16
#define DKk 64
#define Mm 256
#define TD 3072           // 3*D
#define Rr (Bb*Nn)        // 16384
#define BH (Bb*Hh)        // 64
#define SPLITS 8
#define EPSc 1e-6f

// ---------------- scratch (device globals; no cudaMalloc allowed) -----------
__device__ float g_qkv[(size_t)Rr*TD];            // 192 MB
__device__ float g_Qp[(size_t)BH*Nn*Mm];          // 64 MB
__device__ float g_Kp[(size_t)BH*Nn*Mm];          // 64 MB
__device__ float g_KVp[(size_t)BH*SPLITS*Mm*65];  // 34 MB
__device__ float g_KV[(size_t)BH*Mm*65];          // 4 MB
__device__ float g_ctx[(size_t)Rr*Dd];            // 64 MB
__device__ unsigned char g_mask[Rr];              // normalized pad mask (1 = PAD)

// ---------------- 3xTF32 helpers --------------------------------------------
__device__ __forceinline__ float to_tf32(float x) {
    float r; asm("cvt.rna.tf32.f32 %0, %1;" : "=f"(r) : "f"(x)); return r;
}
__device__ __forceinline__ void mma_tf32(float* c, uint32_t a0, uint32_t a1,
                                         uint32_t a2, uint32_t a3,
                                         uint32_t b0, uint32_t b1) {
    asm volatile(
        "mma.sync.aligned.m16n8k8.row.col.f32.tf32.tf32.f32 "
        "{%0,%1,%2,%3}, {%4,%5,%6,%7}, {%8,%9}, {%0,%1,%2,%3};"
        : "+f"(c[0]), "+f"(c[1]), "+f"(c[2]), "+f"(c[3])
        : "r"(a0), "r"(a1), "r"(a2), "r"(a3), "r"(b0), "r"(b1));
}

// ================= mma.sync NT GEMM (3xTF32, double-buffered) ===============
// C[R x Ccols] = A[R x K] @ W[Ccols x K]^T + bias, optional row mask.
// Block 128x128, BK=32, 256 threads = 8 warps (2m x 4n), warp tile 64x32.
#define MBM 128
#define MBN 128
#define MBK 32
#define PADF 36
#define MG_BUF (4*128*PADF)           // floats per buffer (AH, AL, BH, BL)
#define MG_SMEM (2*MG_BUF*4)          // 147456 bytes

__global__ __launch_bounds__(256) void mma_gemm_kernel(
    const float* __restrict__ A, const float* __restrict__ W,
    const float* __restrict__ bias, float* __restrict__ C,
    int K, int Ccols, const unsigned char* __restrict__ pad)
{
    extern __shared__ float sm[];
    int tid = threadIdx.x, wid = tid >> 5, tl = tid & 31;
    int wm = wid & 1, wn = wid >> 1;
    int row0 = blockIdx.y * MBM, col0 = blockIdx.x * MBN;
    const float* Abase = A + (size_t)row0 * K;
    const float* Wbase = W + (size_t)col0 * K;
    int ar = tl >> 2, ac = tl & 3;

    float acc[4][4][4];
    #pragma unroll
    for (int i = 0; i < 4; i++)
        #pragma unroll
        for (int j = 0; j < 4; j++)
            #pragma unroll
            for (int e = 0; e < 4; e++) acc[i][j][e] = 0.f;

    float4 a4[4], b4[4];
    #pragma unroll
    for (int j = 0; j < 4; j++) {
        int idx = j*256 + tid;
        a4[j] = *(const float4*)(Abase + (size_t)(idx>>3) * K + (idx&7)*4);
        b4[j] = *(const float4*)(Wbase + (size_t)(idx>>3) * K + (idx&7)*4);
    }

    const int NK = K / MBK;
    for (int i = 0; i < NK; i++) {
        float* buf = sm + (i & 1) * MG_BUF;
        float* AH = buf;            float* AL = buf + 128*PADF;
        float* BHs = buf + 2*128*PADF; float* BL = buf + 3*128*PADF;
        #pragma unroll
        for (int j = 0; j < 4; j++) {
            int idx = j*256 + tid;
            int off = (idx>>3)*PADF + (idx&7)*4;
            float4 v = a4[j];
            float4 h = make_float4(to_tf32(v.x), to_tf32(v.y), to_tf32(v.z), to_tf32(v.w));
            float4 l = make_float4(to_tf32(v.x-h.x), to_tf32(v.y-h.y),
                                   to_tf32(v.z-h.z), to_tf32(v.w-h.w));
            *(float4*)&AH[off] = h;
            *(float4*)&AL[off] = l;
            v = b4[j];
            h = make_float4(to_tf32(v.x), to_tf32(v.y), to_tf32(v.z), to_tf32(v.w));
            l = make_float4(to_tf32(v.x-h.x), to_tf32(v.y-h.y),
                            to_tf32(v.z-h.z), to_tf32(v.w-h.w));
            *(float4*)&BHs[off] = h;
            *(float4*)&BL[off] = l;
        }
        if (i + 1 < NK) {
            int k0 = (i + 1) * MBK;
            #pragma unroll
            for (int j = 0; j < 4; j++) {
                int idx = j*256 + tid;
                a4[j] = *(const float4*)(Abase + (size_t)(idx>>3) * K + k0 + (idx&7)*4);
                b4[j] = *(const float4*)(Wbase + (size_t)(idx>>3) * K + k0 + (idx&7)*4);
            }
        }
        __syncthreads();
        #pragma unroll
        for (int ks = 0; ks < 4; ks++) {
            int kb = ks * 8;
            uint32_t bh[4][2], bl[4][2];
            #pragma unroll
            for (int ni = 0; ni < 4; ni++) {
                int n = wn*32 + ni*8 + ar;
                bh[ni][0] = __float_as_uint(BHs[n*PADF + kb + ac]);
                bh[ni][1] = __float_as_uint(BHs[n*PADF + kb + 4 + ac]);
                bl[ni][0] = __float_as_uint(BL[n*PADF + kb + ac]);
                bl[ni][1] = __float_as_uint(BL[n*PADF + kb + 4 + ac]);
            }
            #pragma unroll
            for (int mi = 0; mi < 4; mi++) {
                int m = wm*64 + mi*16 + ar;
                uint32_t ah0 = __float_as_uint(AH[m*PADF + kb + ac]);
                uint32_t ah1 = __float_as_uint(AH[(m+8)*PADF + kb + ac]);
                uint32_t ah2 = __float_as_uint(AH[m*PADF + kb + 4 + ac]);
                uint32_t ah3 = __float_as_uint(AH[(m+8)*PADF + kb + 4 + ac]);
                uint32_t al0 = __float_as_uint(AL[m*PADF + kb + ac]);
                uint32_t al1 = __float_as_uint(AL[(m+8)*PADF + kb + ac]);
                uint32_t al2 = __float_as_uint(AL[m*PADF + kb + 4 + ac]);
                uint32_t al3 = __float_as_uint(AL[(m+8)*PADF + kb + 4 + ac]);
                #pragma unroll
                for (int ni = 0; ni < 4; ni++) {
                    mma_tf32(acc[mi][ni], ah0, ah1, ah2, ah3, bh[ni][0], bh[ni][1]);
                    mma_tf32(acc[mi][ni], ah0, ah1, ah2, ah3, bl[ni][0], bl[ni][1]);
                    mma_tf32(acc[mi][ni], al0, al1, al2, al3, bh[ni][0], bh[ni][1]);
                }
            }
        }
    }

    #pragma unroll
    for (int mi = 0; mi < 4; mi++) {
        int r0 = row0 + wm*64 + mi*16 + ar;
        float vm0 = 1.0f, vm1 = 1.0f;
        if (pad) { vm0 = pad[r0] ? 0.0f : 1.0f; vm1 = pad[r0+8] ? 0.0f : 1.0f; }
        #pragma unroll
        for (int ni = 0; ni < 4; ni++) {
            int c = col0 + wn*32 + ni*8 + ac*2;
            float b0 = bias[c], b1 = bias[c+1];
            *(float2*)&C[(size_t)r0 * Ccols + c] =
                make_float2((acc[mi][ni][0] + b0) * vm0, (acc[mi][ni][1] + b1) * vm0);
            *(float2*)&C[(size_t)(r0+8) * Ccols + c] =
                make_float2((acc[mi][ni][2] + b0) * vm1, (acc[mi][ni][3] + b1) * vm1);
        }
    }
}

// ---------------- mask dtype sniffing + normalization -----------------------
__global__ __launch_bounds__(1024) void normalize_mask_kernel(const unsigned char* raw)
{
    __shared__ int wide_bytes;
    const unsigned int* w = (const unsigned int*)raw;
    int t = threadIdx.x;
    if (t == 0) wide_bytes = 0;
    __syncthreads();
    int bad = 0;
    for (int i = t; i < Rr/4; i += 1024)
        if (w[i] > 1u) bad = 1;
    if (bad) atomicOr(&wide_bytes, 1);
    __syncthreads();
    if (wide_bytes) {
        for (int i = t; i < Rr; i += 1024) g_mask[i] = raw[i] ? 1 : 0;
    } else {
        for (int i = t; i < Rr; i += 1024) g_mask[i] = w[i] ? 1 : 0;
    }
}

// ---------------- fast exp (FMA-pipe, avoids MUFU bottleneck) ---------------
__device__ __forceinline__ float fast_exp_neg(float z) {
    float y = z * 1.4426950408889634f;
    y = fmaxf(y, -125.0f);
    float t = y + 12582912.0f;
    int   i = __float_as_int(t) - 0x4B400000;
    float f = y - (t - 12582912.0f);
    float p = 1.5403530393381609e-4f;
    p = fmaf(p, f, 1.3333558146428443e-3f);
    p = fmaf(p, f, 9.618129107628477e-3f);
    p = fmaf(p, f, 5.550410866482158e-2f);
    p = fmaf(p, f, 2.402265069591007e-1f);
    p = fmaf(p, f, 6.931471805599453e-1f);
    p = fmaf(p, f, 1.0f);
    return __int_as_float(__float_as_int(p) + (i << 23));
}

// ================= phi via 3xTF32 mma: proj = t @ omega[h]^T ================
// Block: 64 n-rows x 256 features, one (bh, q/k). K=64 single shot.
// Warp grid 2m x 4n; warp tile 32 rows x 64 features.
#define PADK 68
#define PH_AH 0
#define PH_AL (64*PADK)
#define PH_BH (2*64*PADK)
#define PH_BL (PH_BH + 256*PADK)
#define PH_RM (PH_BH + 2*256*PADK)
#define PHI_SMEM ((PH_RM + 64*4) * 4)          // 175104 bytes

__global__ __launch_bounds__(256) void phi_mma_kernel(
    const float* __restrict__ qkv, const float* __restrict__ omega,
    const unsigned char* __restrict__ pad,
    float* __restrict__ Qp, float* __restrict__ Kp)
{
    extern __shared__ float sm[];
    int tid = threadIdx.x, wid = tid >> 5, tl = tid & 31;
    int wm = wid & 1, wn = wid >> 1;
    int ar = tl >> 2, ac = tl & 3;
    int bh = blockIdx.y; int b = bh >> 4, h = bh & 15;
    int qk = blockIdx.z;
    int n0 = blockIdx.x * 64;

    // A tile: 64 rows x 64 k (hi/lo split)
    #pragma unroll
    for (int j = 0; j < 4; j++) {
        int idx = j*256 + tid;
        int row = idx >> 4, c4 = (idx & 15) * 4;
        const float* tp = qkv + (size_t)(b*Nn + n0 + row) * TD + qk * Dd + h * DKk;
        float4 v = *(const float4*)(tp + c4);
        float4 hh = make_float4(to_tf32(v.x), to_tf32(v.y), to_tf32(v.z), to_tf32(v.w));
        float4 ll = make_float4(to_tf32(v.x-hh.x), to_tf32(v.y-hh.y),
                                to_tf32(v.z-hh.z), to_tf32(v.w-hh.w));
        *(float4*)&sm[PH_AH + row*PADK + c4] = hh;
        *(float4*)&sm[PH_AL + row*PADK + c4] = ll;
    }
    // B tile: omega[h], 256 features x 64 k (hi/lo split)
    #pragma unroll
    for (int j = 0; j < 16; j++) {
        int idx = j*256 + tid;
        int row = idx >> 4, c4 = (idx & 15) * 4;
        const float* op = omega + ((size_t)h * Mm + row) * DKk;
        float4 v = *(const float4*)(op + c4);
        float4 hh = make_float4(to_tf32(v.x), to_tf32(v.y), to_tf32(v.z), to_tf32(v.w));
        float4 ll = make_float4(to_tf32(v.x-hh.x), to_tf32(v.y-hh.y),
                                to_tf32(v.z-hh.z), to_tf32(v.w-hh.w));
        *(float4*)&sm[PH_BH + row*PADK + c4] = hh;
        *(float4*)&sm[PH_BL + row*PADK + c4] = ll;
    }
    __syncthreads();

    float acc[2][8][4];
    #pragma unroll
    for (int i = 0; i < 2; i++)
        #pragma unroll
        for (int j = 0; j < 8; j++)
            #pragma unroll
            for (int e = 0; e < 4; e++) acc[i][j][e] = 0.f;

    #pragma unroll
    for (int ks = 0; ks < 8; ks++) {
        int kb = ks * 8;
        uint32_t bhf[8][2], blf[8][2];
        #pragma unroll
        for (int ni = 0; ni < 8; ni++) {
            int n = wn*64 + ni*8 + ar;
            bhf[ni][0] = __float_as_uint(sm[PH_BH + n*PADK + kb + ac]);
            bhf[ni][1] = __float_as_uint(sm[PH_BH + n*PADK + kb + 4 + ac]);
            blf[ni][0] = __float_as_uint(sm[PH_BL + n*PADK + kb + ac]);
            blf[ni][1] = __float_as_uint(sm[PH_BL + n*PADK + kb + 4 + ac]);
        }
        #pragma unroll
        for (int mi = 0; mi < 2; mi++) {
            int m = wm*32 + mi*16 + ar;
            uint32_t ah0 = __float_as_uint(sm[PH_AH + m*PADK + kb + ac]);
            uint32_t ah1 = __float_as_uint(sm[PH_AH + (m+8)*PADK + kb + ac]);
            uint32_t ah2 = __float_as_uint(sm[PH_AH + m*PADK + kb + 4 + ac]);
            uint32_t ah3 = __float_as_uint(sm[PH_AH + (m+8)*PADK + kb + 4 + ac]);
            uint32_t al0 = __float_as_uint(sm[PH_AL + m*PADK + kb + ac]);
            uint32_t al1 = __float_as_uint(sm[PH_AL + (m+8)*PADK + kb + ac]);
            uint32_t al2 = __float_as_uint(sm[PH_AL + m*PADK + kb + 4 + ac]);
            uint32_t al3 = __float_as_uint(sm[PH_AL + (m+8)*PADK + kb + 4 + ac]);
            #pragma unroll
            for (int ni = 0; ni < 8; ni++) {
                mma_tf32(acc[mi][ni], ah0, ah1, ah2, ah3, bhf[ni][0], bhf[ni][1]);
                mma_tf32(acc[mi][ni], ah0, ah1, ah2, ah3, blf[ni][0], blf[ni][1]);
                mma_tf32(acc[mi][ni], al0, al1, al2, al3, bhf[ni][0], bhf[ni][1]);
            }
        }
    }

    // row max: per lane over 16 vals/row, shfl over ac-quad, smem across wn
    #pragma unroll
    for (int mi = 0; mi < 2; mi++) {
        float m0 = -1e30f, m1 = -1e30f;
        #pragma unroll
        for (int ni = 0; ni < 8; ni++) {
            m0 = fmaxf(m0, fmaxf(acc[mi][ni][0], acc[mi][ni][1]));
            m1 = fmaxf(m1, fmaxf(acc[mi][ni][2], acc[mi][ni][3]));
        }
        #pragma unroll
        for (int o = 1; o <= 2; o <<= 1) {
            m0 = fmaxf(m0, __shfl_xor_sync(0xffffffffu, m0, o));
            m1 = fmaxf(m1, __shfl_xor_sync(0xffffffffu, m1, o));
        }
        if (ac == 0) {
            int r = wm*32 + mi*16 + ar;
            sm[PH_RM + r*4 + wn] = m0;
            sm[PH_RM + (r+8)*4 + wn] = m1;
        }
    }
    __syncthreads();

    float* outp = qk ? Kp : Qp;
    #pragma unroll
    for (int mi = 0; mi < 2; mi++) {
        int r = wm*32 + mi*16 + ar;
        float mx0 = fmaxf(fmaxf(sm[PH_RM + r*4], sm[PH_RM + r*4+1]),
                          fmaxf(sm[PH_RM + r*4+2], sm[PH_RM + r*4+3]));
        float mx1 = fmaxf(fmaxf(sm[PH_RM + (r+8)*4], sm[PH_RM + (r+8)*4+1]),
                          fmaxf(sm[PH_RM + (r+8)*4+2], sm[PH_RM + (r+8)*4+3]));
        float s0 = 0.0625f, s1 = 0.0625f;
        if (qk) {
            if (pad[b*Nn + n0 + r]) s0 = 0.0f;
            if (pad[b*Nn + n0 + r + 8]) s1 = 0.0f;
        }
        float* d0 = outp + ((size_t)bh * Nn + n0 + r) * Mm;
        float* d1 = outp + ((size_t)bh * Nn + n0 + r + 8) * Mm;
        #pragma unroll
        for (int ni = 0; ni < 8; ni++) {
            int c = wn*64 + ni*8 + ac*2;
            *(float2*)(d0 + c) = make_float2(
                fast_exp_neg(acc[mi][ni][0] - mx0) * s0,
                fast_exp_neg(acc[mi][ni][1] - mx0) * s0);
            *(float2*)(d1 + c) = make_float2(
                fast_exp_neg(acc[mi][ni][2] - mx1) * s1,
                fast_exp_neg(acc[mi][ni][3] - mx1) * s1);
        }
    }
}

// ---------------- KV partial: KVp[bh][s][m][d<64]=sum Kp*V ; col64 = ksum ---
__global__ __launch_bounds__(256) void kv_kernel(
    const float* __restrict__ Kp, const float* __restrict__ qkv,
    float* __restrict__ KVp)
{
    __shared__ float kps[32*260];
    __shared__ float vs[32*68];
    int tid = threadIdx.x;
    int s = blockIdx.x, bh = blockIdx.y;
    int b = bh >> 4, h = bh & 15;
    int tm = tid & 63, td = tid >> 6;
    float acc[4][16] = {};
    float ks[4] = {0.f, 0.f, 0.f, 0.f};

    for (int n0 = s * (Nn/SPLITS); n0 < (s+1) * (Nn/SPLITS); n0 += 32) {
        __syncthreads();
        {
            int r = tid >> 3; int f = tid & 7;
            const float* src = Kp + ((size_t)bh * Nn + n0 + r) * Mm;
            #pragma unroll
            for (int j = 0; j < 8; j++) {
                float4 v = *(const float4*)(src + (f + j*8) * 4);
                *(float4*)&kps[r*260 + (f + j*8)*4] = v;
            }
        }
        {
            int r = tid >> 3; int d0 = (tid & 7) * 8;
            const float* src = qkv + (size_t)(b*Nn + n0 + r) * TD + 2*Dd + h*DKk;
            *(float4*)&vs[r*68 + d0]     = *(const float4*)(src + d0);
            *(float4*)&vs[r*68 + d0 + 4] = *(const float4*)(src + d0 + 4);
        }
        __syncthreads();
        #pragma unroll 2
        for (int nn = 0; nn < 32; nn++) {
            float4 k4 = *(const float4*)&kps[nn*260 + tm*4];
            float kk[4] = {k4.x, k4.y, k4.z, k4.w};
            if (td == 0) {
                ks[0] += kk[0]; ks[1] += kk[1]; ks[2] += kk[2]; ks[3] += kk[3];
            }
            float4 v0 = *(const float4*)&vs[nn*68 + td*16];
            float4 v1 = *(const float4*)&vs[nn*68 + td*16 + 4];
            float4 v2 = *(const float4*)&vs[nn*68 + td*16 + 8];
            float4 v3 = *(const float4*)&vs[nn*68 + td*16 + 12];
            float vv[16] = {v0.x,v0.y,v0.z,v0.w, v1.x,v1.y,v1.z,v1.w,
                            v2.x,v2.y,v2.z,v2.w, v3.x,v3.y,v3.z,v3.w};
            #pragma unroll
            for (int j = 0; j < 4; j++)
                #pragma unroll
                for (int dd = 0; dd < 16; dd++)
                    acc[j][dd] = fmaf(kk[j], vv[dd], acc[j][dd]);
        }
    }
    size_t base = ((size_t)(bh * SPLITS + s)) * Mm * 65;
    #pragma unroll
    for (int j = 0; j < 4; j++) {
        int m = tm*4 + j;
        #pragma unroll
        for (int dd = 0; dd < 16; dd++)
            KVp[base + (size_t)m*65 + td*16 + dd] = acc[j][dd];
        if (td == 0) KVp[base + (size_t)m*65 + 64] = ks[j];
    }
}

__global__ void kv_reduce_kernel(const float* __restrict__ KVp, float* __restrict__ KV)
{
    int e = blockIdx.x * blockDim.x + threadIdx.x;
    const int per = Mm * 65;
    if (e >= BH * per) return;
    int bh = e / per; int r = e - bh * per;
    float sum = 0.f;
    #pragma unroll
    for (int sp = 0; sp < SPLITS; sp++)
        sum += KVp[((size_t)(bh * SPLITS + sp)) * per + r];
    KV[e] = sum;
}

// ---------------- ctx = (Qp@KV) / (Qp@ksum + eps) ---------------------------
#define CTX_SMEM ((256*68 + 32*68 + 64) * 4)
__global__ __launch_bounds__(256) void ctx_kernel(
    const float* __restrict__ Qp, const float* __restrict__ KV,
    float* __restrict__ ctx)
{
    extern __shared__ float smf[];
    float* kvs   = smf;
    float* qs    = smf + 256*68;
    float* den_s = qs + 32*68;
    int tid = threadIdx.x;
    int bh = blockIdx.y; int b = bh >> 4, h = bh & 15;
    int n0 = blockIdx.x * 64;

    for (int e = tid; e < Mm*65; e += 256) {
        int m = e / 65, d = e - m*65;
        kvs[m*68 + d] = KV[(size_t)bh * Mm * 65 + e];
    }
    int ty = tid >> 4, tx = tid & 15;
    float acc[4][4] = {};
    float den = 0.f;
    for (int k0 = 0; k0 < Mm; k0 += 32) {
        int lr = tid >> 2; int lk = (tid & 3) * 8;
        const float* src = Qp + ((size_t)bh * Nn + n0 + lr) * Mm + k0 + lk;
        float4 v0 = *(const float4*)src;
        float4 v1 = *(const float4*)(src + 4);
        __syncthreads();
        qs[(lk+0)*68+lr] = v0.x; qs[(lk+1)*68+lr] = v0.y;
        qs[(lk+2)*68+lr] = v0.z; qs[(lk+3)*68+lr] = v0.w;
        qs[(lk+4)*68+lr] = v1.x; qs[(lk+5)*68+lr] = v1.y;
        qs[(lk+6)*68+lr] = v1.z; qs[(lk+7)*68+lr] = v1.w;
        __syncthreads();
        #pragma unroll 8
        for (int k = 0; k < 32; k++) {
            float4 qv = *(const float4*)&qs[k*68 + ty*4];
            float4 wv = *(const float4*)&kvs[(k0+k)*68 + tx*4];
            float q[4] = {qv.x, qv.y, qv.z, qv.w};
            float w[4] = {wv.x, wv.y, wv.z, wv.w};
            #pragma unroll
            for (int i = 0; i < 4; i++)
                #pragma unroll
                for (int j = 0; j < 4; j++)
                    acc[i][j] = fmaf(q[i], w[j], acc[i][j]);
        }
        if (tid < 64) {
            #pragma unroll 8
            for (int k = 0; k < 32; k++)
                den = fmaf(qs[k*68 + tid], kvs[(k0+k)*68 + 64], den);
        }
    }
    if (tid < 64) den_s[tid] = den;
    __syncthreads();
    #pragma unroll
    for (int i = 0; i < 4; i++) {
        int n = n0 + ty*4 + i;
        float dv = den_s[ty*4 + i] + EPSc;
        float inv = 1.0f / dv;
        #pragma unroll
        for (int j = 0; j < 4; j++)
            ctx[(size_t)(b*Nn + n) * Dd + h*DKk + tx*4 + j] = acc[i][j] * inv;
    }
}

// ---------------- launch ----------------------------------------------------
extern "C" void kernel_launch(void* const* d_in, const int* in_sizes, int n_in,
                              void* d_out, int out_size)
{
    const float *x = 0, *Wqkv = 0, *bqkv = 0, *Wout = 0, *bout = 0, *omega = 0;
    const unsigned char* mraw = 0;
    for (int i = 0; i < n_in; i++) {
        switch (in_sizes[i]) {
            case 16777216: x     = (const float*)d_in[i]; break;
            case 16384:    mraw  = (const unsigned char*)d_in[i]; break;
            case 3145728:  Wqkv  = (const float*)d_in[i]; break;
            case 3072:     bqkv  = (const float*)d_in[i]; break;
            case 1048576:  Wout  = (const float*)d_in[i]; break;
            case 1024:     bout  = (const float*)d_in[i]; break;
            case 262144:   omega = (const float*)d_in[i]; break;
            default: break;
        }
    }
    float* out = (float*)d_out;

    float *qkv, *Qp, *Kp, *KVp, *KV, *ctx;
    unsigned char* mask;
    cudaGetSymbolAddress((void**)&qkv,  g_qkv);
    cudaGetSymbolAddress((void**)&Qp,   g_Qp);
    cudaGetSymbolAddress((void**)&Kp,   g_Kp);
    cudaGetSymbolAddress((void**)&KVp,  g_KVp);
    cudaGetSymbolAddress((void**)&KV,   g_KV);
    cudaGetSymbolAddress((void**)&ctx,  g_ctx);
    cudaGetSymbolAddress((void**)&mask, g_mask);

    cudaFuncSetAttribute(phi_mma_kernel, cudaFuncAttributeMaxDynamicSharedMemorySize, PHI_SMEM);
    cudaFuncSetAttribute(ctx_kernel, cudaFuncAttributeMaxDynamicSharedMemorySize, CTX_SMEM);
    cudaFuncSetAttribute(mma_gemm_kernel, cudaFuncAttributeMaxDynamicSharedMemorySize, MG_SMEM);

    // 0) sniff mask dtype and normalize to uint8
    normalize_mask_kernel<<<1, 1024>>>(mraw);
    // 1) qkv = x @ Wqkv^T + bqkv   (mma.sync 3xTF32, double-buffered)
    mma_gemm_kernel<<<dim3(TD/MBN, Rr/MBM), 256, MG_SMEM>>>(
        x, Wqkv, bqkv, qkv, Dd, TD, nullptr);
    // 2) Qp / Kp features (mma.sync 3xTF32)
    phi_mma_kernel<<<dim3(Nn/64, BH, 2), 256, PHI_SMEM>>>(qkv, omega, mask, Qp, Kp);
    // 3) KV + ksum (split-K, deterministic two-stage)
    kv_kernel<<<dim3(SPLITS, BH), 256>>>(Kp, qkv, KVp);
    kv_reduce_kernel<<<(BH*Mm*65 + 255)/256, 256>>>(KVp, KV);
    // 4) ctx
    ctx_kernel<<<dim3(Nn/64, BH), 256, CTX_SMEM>>>(Qp, KV, ctx);
    // 5) out = (ctx @ Wout^T + bout) * valid   (mma.sync 3xTF32, double-buffered)
    mma_gemm_kernel<<<dim3(Dd/MBN, Rr/MBM), 256, MG_SMEM>>>(
        ctx, Wout, bout, out, Dd, Dd, mask);
}

// round 6
// speedup vs baseline: 2.5853x; 1.6255x over previous
#include <cuda_runtime.h>
#include <cuda_bf16.h>
#include <cstdint>

#define Bb 4
#define Nn 4096
#define Dd 1024
#define Hh 16
#define DKk 64
#define Mm 256
#define TD 3072           // 3*D
#define Rr (Bb*Nn)        // 16384
#define BH (Bb*Hh)        // 64
#define SPLITS 8
#define EPSc 1e-6f

// ---------------- scratch (device globals; no cudaMalloc allowed) -----------
__device__ float g_qkv[(size_t)Rr*TD];            // 192 MB
__device__ float g_Qp[(size_t)BH*Nn*Mm];          // 64 MB
__device__ float g_Kp[(size_t)BH*Nn*Mm];          // 64 MB
__device__ float g_KVp[(size_t)BH*SPLITS*Mm*65];  // 34 MB
__device__ float g_ctx[(size_t)Rr*Dd];            // 64 MB
__device__ uint32_t g_KVth[(size_t)BH*80*128];    // KV^T hi (bf16x2 pairs), 2.6MB
__device__ uint32_t g_KVtl[(size_t)BH*80*128];    // KV^T lo
__device__ unsigned char g_mask[Rr];              // normalized pad mask (1 = PAD)

// ---------------- bf16 split helpers ----------------------------------------
// pack(e0,e1): reg.lo = bf16(e0) (even k), reg.hi = bf16(e1) (odd k)
__device__ __forceinline__ uint32_t pkbf(float e0, float e1) {
    uint32_t r; asm("cvt.rn.bf16x2.f32 %0, %1, %2;" : "=r"(r) : "f"(e1), "f"(e0));
    return r;
}
// split float pair -> (hi pair, lo pair)
__device__ __forceinline__ void split2(float v0, float v1, uint32_t& hp, uint32_t& lp) {
    hp = pkbf(v0, v1);
    float h0 = __uint_as_float(hp << 16);
    float h1 = __uint_as_float(hp & 0xFFFF0000u);
    lp = pkbf(v0 - h0, v1 - h1);
}
__device__ __forceinline__ void mma_bf16(float* c, uint32_t a0, uint32_t a1,
                                         uint32_t a2, uint32_t a3,
                                         uint32_t b0, uint32_t b1) {
    asm volatile(
        "mma.sync.aligned.m16n8k16.row.col.f32.bf16.bf16.f32 "
        "{%0,%1,%2,%3}, {%4,%5,%6,%7}, {%8,%9}, {%0,%1,%2,%3};"
        : "+f"(c[0]), "+f"(c[1]), "+f"(c[2]), "+f"(c[3])
        : "r"(a0), "r"(a1), "r"(a2), "r"(a3), "r"(b0), "r"(b1));
}
// tf32 (for phi)
__device__ __forceinline__ float to_tf32(float x) {
    float r; asm("cvt.rna.tf32.f32 %0, %1;" : "=f"(r) : "f"(x)); return r;
}
__device__ __forceinline__ void mma_tf32(float* c, uint32_t a0, uint32_t a1,
                                         uint32_t a2, uint32_t a3,
                                         uint32_t b0, uint32_t b1) {
    asm volatile(
        "mma.sync.aligned.m16n8k8.row.col.f32.tf32.tf32.f32 "
        "{%0,%1,%2,%3}, {%4,%5,%6,%7}, {%8,%9}, {%0,%1,%2,%3};"
        : "+f"(c[0]), "+f"(c[1]), "+f"(c[2]), "+f"(c[3])
        : "r"(a0), "r"(a1), "r"(a2), "r"(a3), "r"(b0), "r"(b1));
}

// ================= 3x bf16 NT GEMM (double-buffered) ========================
// C[R x Ccols] = A[R x K] @ W[Ccols x K]^T + bias, optional row mask.
// Block 128x128, BK=32 (16 bf16-pairs/row), 8 warps (2m x 4n), warp 64x32.
#define MBM 128
#define MBN 128
#define PADU 20                        // uint32 pairs per row (16 + 4 pad)
#define MG_BUF (4*128*PADU)            // uint32 per buffer (AH,AL,BH,BL)
#define MG_SMEM (2*MG_BUF*4)           // 81920 bytes

__global__ __launch_bounds__(256) void mma_gemm_kernel(
    const float* __restrict__ A, const float* __restrict__ W,
    const float* __restrict__ bias, float* __restrict__ C,
    int K, int Ccols, const unsigned char* __restrict__ pad)
{
    extern __shared__ uint32_t smu[];
    int tid = threadIdx.x, wid = tid >> 5, tl = tid & 31;
    int wm = wid & 1, wn = wid >> 1;
    int row0 = blockIdx.y * MBM, col0 = blockIdx.x * MBN;
    const float* Abase = A + (size_t)row0 * K;
    const float* Wbase = W + (size_t)col0 * K;
    int ar = tl >> 2, ac = tl & 3;

    float acc[4][4][4];
    #pragma unroll
    for (int i = 0; i < 4; i++)
        #pragma unroll
        for (int j = 0; j < 4; j++)
            #pragma unroll
            for (int e = 0; e < 4; e++) acc[i][j][e] = 0.f;

    float4 a4[4], b4[4];
    #pragma unroll
    for (int j = 0; j < 4; j++) {
        int idx = j*256 + tid;
        a4[j] = *(const float4*)(Abase + (size_t)(idx>>3) * K + (idx&7)*4);
        b4[j] = *(const float4*)(Wbase + (size_t)(idx>>3) * K + (idx&7)*4);
    }

    const int NK = K / 32;
    for (int i = 0; i < NK; i++) {
        uint32_t* buf = smu + (i & 1) * MG_BUF;
        uint32_t* AH = buf;              uint32_t* AL = buf + 128*PADU;
        uint32_t* BHs = buf + 2*128*PADU; uint32_t* BL = buf + 3*128*PADU;
        #pragma unroll
        for (int j = 0; j < 4; j++) {
            int idx = j*256 + tid;
            int off = (idx>>3)*PADU + (idx&7)*2;
            uint32_t h0, l0, h1, l1;
            split2(a4[j].x, a4[j].y, h0, l0);
            split2(a4[j].z, a4[j].w, h1, l1);
            *(uint2*)&AH[off] = make_uint2(h0, h1);
            *(uint2*)&AL[off] = make_uint2(l0, l1);
            split2(b4[j].x, b4[j].y, h0, l0);
            split2(b4[j].z, b4[j].w, h1, l1);
            *(uint2*)&BHs[off] = make_uint2(h0, h1);
            *(uint2*)&BL[off] = make_uint2(l0, l1);
        }
        if (i + 1 < NK) {
            int k0 = (i + 1) * 32;
            #pragma unroll
            for (int j = 0; j < 4; j++) {
                int idx = j*256 + tid;
                a4[j] = *(const float4*)(Abase + (size_t)(idx>>3) * K + k0 + (idx&7)*4);
                b4[j] = *(const float4*)(Wbase + (size_t)(idx>>3) * K + k0 + (idx&7)*4);
            }
        }
        __syncthreads();
        #pragma unroll
        for (int s = 0; s < 2; s++) {
            int base = s * 8;
            uint32_t bhf[4][2], blf[4][2];
            #pragma unroll
            for (int ni = 0; ni < 4; ni++) {
                int n = wn*32 + ni*8 + ar;
                bhf[ni][0] = BHs[n*PADU + base + ac];
                bhf[ni][1] = BHs[n*PADU + base + 4 + ac];
                blf[ni][0] = BL[n*PADU + base + ac];
                blf[ni][1] = BL[n*PADU + base + 4 + ac];
            }
            #pragma unroll
            for (int mi = 0; mi < 4; mi++) {
                int m = wm*64 + mi*16 + ar;
                uint32_t ah0 = AH[m*PADU + base + ac];
                uint32_t ah1 = AH[(m+8)*PADU + base + ac];
                uint32_t ah2 = AH[m*PADU + base + 4 + ac];
                uint32_t ah3 = AH[(m+8)*PADU + base + 4 + ac];
                uint32_t al0 = AL[m*PADU + base + ac];
                uint32_t al1 = AL[(m+8)*PADU + base + ac];
                uint32_t al2 = AL[m*PADU + base + 4 + ac];
                uint32_t al3 = AL[(m+8)*PADU + base + 4 + ac];
                #pragma unroll
                for (int ni = 0; ni < 4; ni++) {
                    mma_bf16(acc[mi][ni], ah0, ah1, ah2, ah3, bhf[ni][0], bhf[ni][1]);
                    mma_bf16(acc[mi][ni], ah0, ah1, ah2, ah3, blf[ni][0], blf[ni][1]);
                    mma_bf16(acc[mi][ni], al0, al1, al2, al3, bhf[ni][0], bhf[ni][1]);
                }
            }
        }
    }

    #pragma unroll
    for (int mi = 0; mi < 4; mi++) {
        int r0 = row0 + wm*64 + mi*16 + ar;
        float vm0 = 1.0f, vm1 = 1.0f;
        if (pad) { vm0 = pad[r0] ? 0.0f : 1.0f; vm1 = pad[r0+8] ? 0.0f : 1.0f; }
        #pragma unroll
        for (int ni = 0; ni < 4; ni++) {
            int c = col0 + wn*32 + ni*8 + ac*2;
            float b0 = bias[c], b1 = bias[c+1];
            *(float2*)&C[(size_t)r0 * Ccols + c] =
                make_float2((acc[mi][ni][0] + b0) * vm0, (acc[mi][ni][1] + b1) * vm0);
            *(float2*)&C[(size_t)(r0+8) * Ccols + c] =
                make_float2((acc[mi][ni][2] + b0) * vm1, (acc[mi][ni][3] + b1) * vm1);
        }
    }
}

// ---------------- mask dtype sniffing + normalization -----------------------
__global__ __launch_bounds__(1024) void normalize_mask_kernel(const unsigned char* raw)
{
    __shared__ int wide_bytes;
    const unsigned int* w = (const unsigned int*)raw;
    int t = threadIdx.x;
    if (t == 0) wide_bytes = 0;
    __syncthreads();
    int bad = 0;
    for (int i = t; i < Rr/4; i += 1024)
        if (w[i] > 1u) bad = 1;
    if (bad) atomicOr(&wide_bytes, 1);
    __syncthreads();
    if (wide_bytes) {
        for (int i = t; i < Rr; i += 1024) g_mask[i] = raw[i] ? 1 : 0;
    } else {
        for (int i = t; i < Rr; i += 1024) g_mask[i] = w[i] ? 1 : 0;
    }
}

// ---------------- fast exp (FMA-pipe) ---------------------------------------
__device__ __forceinline__ float fast_exp_neg(float z) {
    float y = z * 1.4426950408889634f;
    y = fmaxf(y, -125.0f);
    float t = y + 12582912.0f;
    int   i = __float_as_int(t) - 0x4B400000;
    float f = y - (t - 12582912.0f);
    float p = 1.5403530393381609e-4f;
    p = fmaf(p, f, 1.3333558146428443e-3f);
    p = fmaf(p, f, 9.618129107628477e-3f);
    p = fmaf(p, f, 5.550410866482158e-2f);
    p = fmaf(p, f, 2.402265069591007e-1f);
    p = fmaf(p, f, 6.931471805599453e-1f);
    p = fmaf(p, f, 1.0f);
    return __int_as_float(__float_as_int(p) + (i << 23));
}

// ================= phi via 3xTF32 mma: proj = t @ omega[h]^T ================
#define PADK 68
#define PH_AH 0
#define PH_AL (64*PADK)
#define PH_BH (2*64*PADK)
#define PH_BL (PH_BH + 256*PADK)
#define PH_RM (PH_BH + 2*256*PADK)
#define PHI_SMEM ((PH_RM + 64*4) * 4)

__global__ __launch_bounds__(256) void phi_mma_kernel(
    const float* __restrict__ qkv, const float* __restrict__ omega,
    const unsigned char* __restrict__ pad,
    float* __restrict__ Qp, float* __restrict__ Kp)
{
    extern __shared__ float sm[];
    int tid = threadIdx.x, wid = tid >> 5, tl = tid & 31;
    int wm = wid & 1, wn = wid >> 1;
    int ar = tl >> 2, ac = tl & 3;
    int bh = blockIdx.y; int b = bh >> 4, h = bh & 15;
    int qk = blockIdx.z;
    int n0 = blockIdx.x * 64;

    #pragma unroll
    for (int j = 0; j < 4; j++) {
        int idx = j*256 + tid;
        int row = idx >> 4, c4 = (idx & 15) * 4;
        const float* tp = qkv + (size_t)(b*Nn + n0 + row) * TD + qk * Dd + h * DKk;
        float4 v = *(const float4*)(tp + c4);
        float4 hh = make_float4(to_tf32(v.x), to_tf32(v.y), to_tf32(v.z), to_tf32(v.w));
        float4 ll = make_float4(to_tf32(v.x-hh.x), to_tf32(v.y-hh.y),
                                to_tf32(v.z-hh.z), to_tf32(v.w-hh.w));
        *(float4*)&sm[PH_AH + row*PADK + c4] = hh;
        *(float4*)&sm[PH_AL + row*PADK + c4] = ll;
    }
    #pragma unroll
    for (int j = 0; j < 16; j++) {
        int idx = j*256 + tid;
        int row = idx >> 4, c4 = (idx & 15) * 4;
        const float* op = omega + ((size_t)h * Mm + row) * DKk;
        float4 v = *(const float4*)(op + c4);
        float4 hh = make_float4(to_tf32(v.x), to_tf32(v.y), to_tf32(v.z), to_tf32(v.w));
        float4 ll = make_float4(to_tf32(v.x-hh.x), to_tf32(v.y-hh.y),
                                to_tf32(v.z-hh.z), to_tf32(v.w-hh.w));
        *(float4*)&sm[PH_BH + row*PADK + c4] = hh;
        *(float4*)&sm[PH_BL + row*PADK + c4] = ll;
    }
    __syncthreads();

    float acc[2][8][4];
    #pragma unroll
    for (int i = 0; i < 2; i++)
        #pragma unroll
        for (int j = 0; j < 8; j++)
            #pragma unroll
            for (int e = 0; e < 4; e++) acc[i][j][e] = 0.f;

    #pragma unroll
    for (int ks = 0; ks < 8; ks++) {
        int kb = ks * 8;
        uint32_t bhf[8][2], blf[8][2];
        #pragma unroll
        for (int ni = 0; ni < 8; ni++) {
            int n = wn*64 + ni*8 + ar;
            bhf[ni][0] = __float_as_uint(sm[PH_BH + n*PADK + kb + ac]);
            bhf[ni][1] = __float_as_uint(sm[PH_BH + n*PADK + kb + 4 + ac]);
            blf[ni][0] = __float_as_uint(sm[PH_BL + n*PADK + kb + ac]);
            blf[ni][1] = __float_as_uint(sm[PH_BL + n*PADK + kb + 4 + ac]);
        }
        #pragma unroll
        for (int mi = 0; mi < 2; mi++) {
            int m = wm*32 + mi*16 + ar;
            uint32_t ah0 = __float_as_uint(sm[PH_AH + m*PADK + kb + ac]);
            uint32_t ah1 = __float_as_uint(sm[PH_AH + (m+8)*PADK + kb + ac]);
            uint32_t ah2 = __float_as_uint(sm[PH_AH + m*PADK + kb + 4 + ac]);
            uint32_t ah3 = __float_as_uint(sm[PH_AH + (m+8)*PADK + kb + 4 + ac]);
            uint32_t al0 = __float_as_uint(sm[PH_AL + m*PADK + kb + ac]);
            uint32_t al1 = __float_as_uint(sm[PH_AL + (m+8)*PADK + kb + ac]);
            uint32_t al2 = __float_as_uint(sm[PH_AL + m*PADK + kb + 4 + ac]);
            uint32_t al3 = __float_as_uint(sm[PH_AL + (m+8)*PADK + kb + 4 + ac]);
            #pragma unroll
            for (int ni = 0; ni < 8; ni++) {
                mma_tf32(acc[mi][ni], ah0, ah1, ah2, ah3, bhf[ni][0], bhf[ni][1]);
                mma_tf32(acc[mi][ni], ah0, ah1, ah2, ah3, blf[ni][0], blf[ni][1]);
                mma_tf32(acc[mi][ni], al0, al1, al2, al3, bhf[ni][0], bhf[ni][1]);
            }
        }
    }

    #pragma unroll
    for (int mi = 0; mi < 2; mi++) {
        float m0 = -1e30f, m1 = -1e30f;
        #pragma unroll
        for (int ni = 0; ni < 8; ni++) {
            m0 = fmaxf(m0, fmaxf(acc[mi][ni][0], acc[mi][ni][1]));
            m1 = fmaxf(m1, fmaxf(acc[mi][ni][2], acc[mi][ni][3]));
        }
        #pragma unroll
        for (int o = 1; o <= 2; o <<= 1) {
            m0 = fmaxf(m0, __shfl_xor_sync(0xffffffffu, m0, o));
            m1 = fmaxf(m1, __shfl_xor_sync(0xffffffffu, m1, o));
        }
        if (ac == 0) {
            int r = wm*32 + mi*16 + ar;
            sm[PH_RM + r*4 + wn] = m0;
            sm[PH_RM + (r+8)*4 + wn] = m1;
        }
    }
    __syncthreads();

    float* outp = qk ? Kp : Qp;
    #pragma unroll
    for (int mi = 0; mi < 2; mi++) {
        int r = wm*32 + mi*16 + ar;
        float mx0 = fmaxf(fmaxf(sm[PH_RM + r*4], sm[PH_RM + r*4+1]),
                          fmaxf(sm[PH_RM + r*4+2], sm[PH_RM + r*4+3]));
        float mx1 = fmaxf(fmaxf(sm[PH_RM + (r+8)*4], sm[PH_RM + (r+8)*4+1]),
                          fmaxf(sm[PH_RM + (r+8)*4+2], sm[PH_RM + (r+8)*4+3]));
        float s0 = 0.0625f, s1 = 0.0625f;
        if (qk) {
            if (pad[b*Nn + n0 + r]) s0 = 0.0f;
            if (pad[b*Nn + n0 + r + 8]) s1 = 0.0f;
        }
        float* d0 = outp + ((size_t)bh * Nn + n0 + r) * Mm;
        float* d1 = outp + ((size_t)bh * Nn + n0 + r + 8) * Mm;
        #pragma unroll
        for (int ni = 0; ni < 8; ni++) {
            int c = wn*64 + ni*8 + ac*2;
            *(float2*)(d0 + c) = make_float2(
                fast_exp_neg(acc[mi][ni][0] - mx0) * s0,
                fast_exp_neg(acc[mi][ni][1] - mx0) * s0);
            *(float2*)(d1 + c) = make_float2(
                fast_exp_neg(acc[mi][ni][2] - mx1) * s1,
                fast_exp_neg(acc[mi][ni][3] - mx1) * s1);
        }
    }
}

// ---------------- KV partial: KVp[bh][s][m][d<64]=sum Kp*V ; col64 = ksum ---
__global__ __launch_bounds__(256) void kv_kernel(
    const float* __restrict__ Kp, const float* __restrict__ qkv,
    float* __restrict__ KVp)
{
    __shared__ float kps[32*260];
    __shared__ float vs[32*68];
    int tid = threadIdx.x;
    int s = blockIdx.x, bh = blockIdx.y;
    int b = bh >> 4, h = bh & 15;
    int tm = tid & 63, td = tid >> 6;
    float acc[4][16] = {};
    float ks[4] = {0.f, 0.f, 0.f, 0.f};

    for (int n0 = s * (Nn/SPLITS); n0 < (s+1) * (Nn/SPLITS); n0 += 32) {
        __syncthreads();
        {
            int r = tid >> 3; int f = tid & 7;
            const float* src = Kp + ((size_t)bh * Nn + n0 + r) * Mm;
            #pragma unroll
            for (int j = 0; j < 8; j++) {
                float4 v = *(const float4*)(src + (f + j*8) * 4);
                *(float4*)&kps[r*260 + (f + j*8)*4] = v;
            }
        }
        {
            int r = tid >> 3; int d0 = (tid & 7) * 8;
            const float* src = qkv + (size_t)(b*Nn + n0 + r) * TD + 2*Dd + h*DKk;
            *(float4*)&vs[r*68 + d0]     = *(const float4*)(src + d0);
            *(float4*)&vs[r*68 + d0 + 4] = *(const float4*)(src + d0 + 4);
        }
        __syncthreads();
        #pragma unroll 2
        for (int nn = 0; nn < 32; nn++) {
            float4 k4 = *(const float4*)&kps[nn*260 + tm*4];
            float kk[4] = {k4.x, k4.y, k4.z, k4.w};
            if (td == 0) {
                ks[0] += kk[0]; ks[1] += kk[1]; ks[2] += kk[2]; ks[3] += kk[3];
            }
            float4 v0 = *(const float4*)&vs[nn*68 + td*16];
            float4 v1 = *(const float4*)&vs[nn*68 + td*16 + 4];
            float4 v2 = *(const float4*)&vs[nn*68 + td*16 + 8];
            float4 v3 = *(const float4*)&vs[nn*68 + td*16 + 12];
            float vv[16] = {v0.x,v0.y,v0.z,v0.w, v1.x,v1.y,v1.z,v1.w,
                            v2.x,v2.y,v2.z,v2.w, v3.x,v3.y,v3.z,v3.w};
            #pragma unroll
            for (int j = 0; j < 4; j++)
                #pragma unroll
                for (int dd = 0; dd < 16; dd++)
                    acc[j][dd] = fmaf(kk[j], vv[dd], acc[j][dd]);
        }
    }
    size_t base = ((size_t)(bh * SPLITS + s)) * Mm * 65;
    #pragma unroll
    for (int j = 0; j < 4; j++) {
        int m = tm*4 + j;
        #pragma unroll
        for (int dd = 0; dd < 16; dd++)
            KVp[base + (size_t)m*65 + td*16 + dd] = acc[j][dd];
        if (td == 0) KVp[base + (size_t)m*65 + 64] = ks[j];
    }
}

// --------- reduce splits + emit KV^T (80 x 128 bf16x2 pairs, hi/lo) ---------
// layout: KVth[(bh*80 + d)*128 + mp] = pair (m=2mp, 2mp+1); d=64 is ksum,
// d in [65,80) zero padding.
__global__ void kvt_kernel(const float* __restrict__ KVp,
                           uint32_t* __restrict__ KVth, uint32_t* __restrict__ KVtl)
{
    int e = blockIdx.x * blockDim.x + threadIdx.x;
    if (e >= BH*80*128) return;
    int mp = e & 127; int rest = e >> 7; int d = rest % 80; int bh = rest / 80;
    float s0 = 0.f, s1 = 0.f;
    if (d < 65) {
        int m0 = mp * 2;
        const float* base = KVp + (size_t)bh * SPLITS * Mm * 65;
        #pragma unroll
        for (int sp = 0; sp < SPLITS; sp++) {
            s0 += base[(size_t)sp*Mm*65 + m0*65 + d];
            s1 += base[(size_t)sp*Mm*65 + (m0+1)*65 + d];
        }
    }
    uint32_t hp, lp;
    split2(s0, s1, hp, lp);
    KVth[e] = hp; KVtl[e] = lp;
}

// ---------------- ctx = (Qp@KV) / (Qp@ksum + eps) via 3x bf16 mma -----------
// Block: 64 n-rows x 80 cols (d 0..63 out, 64 = den, 65..79 pad), k = 256.
// 8 warps: 4m x 2n; warp tile 16 rows x 40 cols (5 n-tiles).
#define CPAD 36
#define CT_AH 0
#define CT_AL (64*CPAD)
#define CT_BH (2*64*CPAD)
#define CT_BL (CT_BH + 80*CPAD)
#define CT_DEN (CT_BL + 80*CPAD)
#define CTX_SMEM ((CT_DEN + 64) * 4)    // 41728 bytes

__global__ __launch_bounds__(256) void ctx_mma_kernel(
    const float* __restrict__ Qp, const uint32_t* __restrict__ KVth,
    const uint32_t* __restrict__ KVtl, float* __restrict__ ctx)
{
    extern __shared__ uint32_t smu[];
    float* den_s = (float*)(smu + CT_DEN);
    int tid = threadIdx.x, wid = tid >> 5, tl = tid & 31;
    int wm = wid & 3, wn = wid >> 2;
    int ar = tl >> 2, ac = tl & 3;
    int bh = blockIdx.y; int b = bh >> 4, h = bh & 15;
    int n0 = blockIdx.x * 64;

    float acc[5][4];
    #pragma unroll
    for (int i = 0; i < 5; i++)
        #pragma unroll
        for (int e = 0; e < 4; e++) acc[i][e] = 0.f;

    for (int c = 0; c < 4; c++) {           // k-chunks of 64 m (32 pairs)
        if (c) __syncthreads();
        // A: Qp rows 64 x 64 floats -> split pairs
        #pragma unroll
        for (int j = 0; j < 4; j++) {
            int idx = j*256 + tid;
            int row = idx >> 4, f4 = idx & 15;
            float4 v = *(const float4*)(Qp + ((size_t)bh*Nn + n0 + row)*Mm + c*64 + f4*4);
            uint32_t h0, l0, h1, l1;
            split2(v.x, v.y, h0, l0);
            split2(v.z, v.w, h1, l1);
            int off = row*CPAD + f4*2;
            *(uint2*)&smu[CT_AH + off] = make_uint2(h0, h1);
            *(uint2*)&smu[CT_AL + off] = make_uint2(l0, l1);
        }
        // B: KVt 80 rows x 32 pairs (already bf16x2)
        #pragma unroll
        for (int j = 0; j < 3; j++) {
            int idx = j*256 + tid;
            if (idx < 640) {
                int row = idx >> 3, q4 = idx & 7;
                size_t src = ((size_t)bh*80 + row)*128 + c*32 + q4*4;
                *(uint4*)&smu[CT_BH + row*CPAD + q4*4] = *(const uint4*)&KVth[src];
                *(uint4*)&smu[CT_BL + row*CPAD + q4*4] = *(const uint4*)&KVtl[src];
            }
        }
        __syncthreads();
        #pragma unroll
        for (int s = 0; s < 4; s++) {
            int base = s * 8;
            int m = wm*16 + ar;
            uint32_t ah0 = smu[CT_AH + m*CPAD + base + ac];
            uint32_t ah1 = smu[CT_AH + (m+8)*CPAD + base + ac];
            uint32_t ah2 = smu[CT_AH + m*CPAD + base + 4 + ac];
            uint32_t ah3 = smu[CT_AH + (m+8)*CPAD + base + 4 + ac];
            uint32_t al0 = smu[CT_AL + m*CPAD + base + ac];
            uint32_t al1 = smu[CT_AL + (m+8)*CPAD + base + ac];
            uint32_t al2 = smu[CT_AL + m*CPAD + base + 4 + ac];
            uint32_t al3 = smu[CT_AL + (m+8)*CPAD + base + 4 + ac];
            #pragma unroll
            for (int ni = 0; ni < 5; ni++) {
                int n = wn*40 + ni*8 + ar;
                uint32_t b0h = smu[CT_BH + n*CPAD + base + ac];
                uint32_t b1h = smu[CT_BH + n*CPAD + base + 4 + ac];
                uint32_t b0l = smu[CT_BL + n*CPAD + base + ac];
                uint32_t b1l = smu[CT_BL + n*CPAD + base + 4 + ac];
                mma_bf16(acc[ni], ah0, ah1, ah2, ah3, b0h, b1h);
                mma_bf16(acc[ni], ah0, ah1, ah2, ah3, b0l, b1l);
                mma_bf16(acc[ni], al0, al1, al2, al3, b0h, b1h);
            }
        }
    }
    __syncthreads();
    // den lives at col 64 = wn1, ni3, ac0 (elements 0 and 2)
    if (wn == 1 && ac == 0) {
        int r = wm*16 + ar;
        den_s[r] = acc[3][0];
        den_s[r+8] = acc[3][2];
    }
    __syncthreads();

    int r = wm*16 + ar;
    float inv0 = 1.0f / (den_s[r] + EPSc);
    float inv1 = 1.0f / (den_s[r+8] + EPSc);
    float* dst0 = ctx + (size_t)(b*Nn + n0 + r) * Dd + h*DKk;
    float* dst1 = ctx + (size_t)(b*Nn + n0 + r + 8) * Dd + h*DKk;
    #pragma unroll
    for (int ni = 0; ni < 5; ni++) {
        int col = wn*40 + ni*8 + ac*2;
        if (col < 64) {
            *(float2*)(dst0 + col) = make_float2(acc[ni][0]*inv0, acc[ni][1]*inv0);
            *(float2*)(dst1 + col) = make_float2(acc[ni][2]*inv1, acc[ni][3]*inv1);
        }
    }
}

// ---------------- launch ----------------------------------------------------
extern "C" void kernel_launch(void* const* d_in, const int* in_sizes, int n_in,
                              void* d_out, int out_size)
{
    const float *x = 0, *Wqkv = 0, *bqkv = 0, *Wout = 0, *bout = 0, *omega = 0;
    const unsigned char* mraw = 0;
    for (int i = 0; i < n_in; i++) {
        switch (in_sizes[i]) {
            case 16777216: x     = (const float*)d_in[i]; break;
            case 16384:    mraw  = (const unsigned char*)d_in[i]; break;
            case 3145728:  Wqkv  = (const float*)d_in[i]; break;
            case 3072:     bqkv  = (const float*)d_in[i]; break;
            case 1048576:  Wout  = (const float*)d_in[i]; break;
            case 1024:     bout  = (const float*)d_in[i]; break;
            case 262144:   omega = (const float*)d_in[i]; break;
            default: break;
        }
    }
    float* out = (float*)d_out;

    float *qkv, *Qp, *Kp, *KVp, *ctx;
    uint32_t *KVth, *KVtl;
    unsigned char* mask;
    cudaGetSymbolAddress((void**)&qkv,  g_qkv);
    cudaGetSymbolAddress((void**)&Qp,   g_Qp);
    cudaGetSymbolAddress((void**)&Kp,   g_Kp);
    cudaGetSymbolAddress((void**)&KVp,  g_KVp);
    cudaGetSymbolAddress((void**)&ctx,  g_ctx);
    cudaGetSymbolAddress((void**)&KVth, g_KVth);
    cudaGetSymbolAddress((void**)&KVtl, g_KVtl);
    cudaGetSymbolAddress((void**)&mask, g_mask);

    cudaFuncSetAttribute(phi_mma_kernel, cudaFuncAttributeMaxDynamicSharedMemorySize, PHI_SMEM);
    cudaFuncSetAttribute(ctx_mma_kernel, cudaFuncAttributeMaxDynamicSharedMemorySize, CTX_SMEM);
    cudaFuncSetAttribute(mma_gemm_kernel, cudaFuncAttributeMaxDynamicSharedMemorySize, MG_SMEM);

    // 0) sniff mask dtype and normalize to uint8
    normalize_mask_kernel<<<1, 1024>>>(mraw);
    // 1) qkv = x @ Wqkv^T + bqkv   (3x bf16 mma)
    mma_gemm_kernel<<<dim3(TD/MBN, Rr/MBM), 256, MG_SMEM>>>(
        x, Wqkv, bqkv, qkv, Dd, TD, nullptr);
    // 2) Qp / Kp features (3xTF32 mma)
    phi_mma_kernel<<<dim3(Nn/64, BH, 2), 256, PHI_SMEM>>>(qkv, omega, mask, Qp, Kp);
    // 3) KV + ksum (split-K partials, then reduce into bf16 KV^T)
    kv_kernel<<<dim3(SPLITS, BH), 256>>>(Kp, qkv, KVp);
    kvt_kernel<<<(BH*80*128 + 255)/256, 256>>>(KVp, KVth, KVtl);
    // 4) ctx (3x bf16 mma, den fused as column 64)
    ctx_mma_kernel<<<dim3(Nn/64, BH), 256, CTX_SMEM>>>(Qp, KVth, KVtl, ctx);
    // 5) out = (ctx @ Wout^T + bout) * valid   (3x bf16 mma)
    mma_gemm_kernel<<<dim3(Dd/MBN, Rr/MBM), 256, MG_SMEM>>>(
        ctx, Wout, bout, out, Dd, Dd, mask);
}